// round 1
// baseline (speedup 1.0000x reference)
#include <cuda_runtime.h>
#include <math.h>
#include <stdint.h>

#define Bn   32
#define Sn   1024
#define Dn   512
#define Hn   8
#define Ln   4
#define DHn  64
#define BSn  (Bn*Sn)
#define FCn  32

// ------------------------- scratch (device globals; no allocs allowed) ------
__device__ float g_x[(size_t)BSn * Dn];
__device__ float g_qkv[(size_t)BSn * 3 * Dn];
__device__ float g_ctx[(size_t)BSn * Dn];
__device__ float g_t1[(size_t)BSn * Dn];
__device__ float g_t2[(size_t)BSn * Dn];
__device__ float g_logits[BSn];

// ============================ embed =========================================
// x[b,s,:] = concat(loc[16], time@Wtd+btd (3)) @ Wemb[19,512] + bemb
__global__ void embed_kernel(const float* __restrict__ loc,
                             const float* __restrict__ tdist,
                             const float* __restrict__ Wtd,
                             const float* __restrict__ btd,
                             const float* __restrict__ Wemb,
                             const float* __restrict__ bemb,
                             float* __restrict__ x) {
    int tok = blockIdx.x;                       // 0..BSn-1
    const float* lp = loc + (size_t)tok * 16;
    const float* tp = tdist + (size_t)tok * 8;
    float in[19];
#pragma unroll
    for (int i = 0; i < 16; i++) in[i] = lp[i];
#pragma unroll
    for (int j = 0; j < 3; j++) {
        float s = btd[j];
#pragma unroll
        for (int i = 0; i < 8; i++) s += tp[i] * Wtd[i * 3 + j];
        in[16 + j] = s;
    }
    int d = threadIdx.x * 4;                    // blockDim = 128
    float4 acc = *(const float4*)(bemb + d);
#pragma unroll
    for (int i = 0; i < 19; i++) {
        float4 w = *(const float4*)(Wemb + i * 512 + d);
        float s = in[i];
        acc.x += s * w.x; acc.y += s * w.y; acc.z += s * w.z; acc.w += s * w.w;
    }
    *(float4*)(x + (size_t)tok * 512 + d) = acc;
}

// ============================ SGEMM =========================================
// C[M,N] = act(A[M,K] @ W[K,N] + bias[N]).  M%128==0, N%128==0, K%8==0.
#define GBM 128
#define GBN 128
#define GBK 8
template <int ACT>
__global__ __launch_bounds__(256)
void sgemm_bias(const float* __restrict__ A, const float* __restrict__ W,
                const float* __restrict__ bias, float* __restrict__ C,
                int M, int N, int K) {
    __shared__ float As[GBK][GBM];
    __shared__ float Ws[GBK][GBN];

    const int bm = blockIdx.y * GBM;
    const int bn = blockIdx.x * GBN;
    const int tid = threadIdx.x;
    const int tx = tid & 15;          // 0..15 -> 8 N-cols each
    const int ty = tid >> 4;          // 0..15 -> 8 M-rows each

    const int arow = tid >> 1;              // 0..127
    const int acol = (tid & 1) << 2;        // 0 or 4
    const int wrow = tid >> 5;              // 0..7
    const int wcol = (tid & 31) << 2;       // 0..124

    const float* Ap = A + (size_t)(bm + arow) * K + acol;
    const float* Wp = W + (size_t)wrow * N + bn + wcol;

    float acc[8][8];
#pragma unroll
    for (int i = 0; i < 8; i++)
#pragma unroll
        for (int j = 0; j < 8; j++) acc[i][j] = 0.f;

    for (int k0 = 0; k0 < K; k0 += GBK) {
        float4 av = *(const float4*)(Ap + k0);
        As[acol + 0][arow] = av.x;
        As[acol + 1][arow] = av.y;
        As[acol + 2][arow] = av.z;
        As[acol + 3][arow] = av.w;
        *(float4*)(&Ws[wrow][wcol]) = *(const float4*)(Wp + (size_t)k0 * N);
        __syncthreads();
#pragma unroll
        for (int kk = 0; kk < GBK; kk++) {
            float a[8], b[8];
            *(float4*)(a)     = *(const float4*)(&As[kk][ty * 8]);
            *(float4*)(a + 4) = *(const float4*)(&As[kk][ty * 8 + 4]);
            *(float4*)(b)     = *(const float4*)(&Ws[kk][tx * 8]);
            *(float4*)(b + 4) = *(const float4*)(&Ws[kk][tx * 8 + 4]);
#pragma unroll
            for (int i = 0; i < 8; i++)
#pragma unroll
                for (int j = 0; j < 8; j++) acc[i][j] += a[i] * b[j];
        }
        __syncthreads();
    }

    float bv[8];
#pragma unroll
    for (int j = 0; j < 8; j++) bv[j] = bias[bn + tx * 8 + j];
#pragma unroll
    for (int i = 0; i < 8; i++) {
        size_t row = (size_t)(bm + ty * 8 + i);
        float* cp = C + row * N + bn + tx * 8;
#pragma unroll
        for (int j = 0; j < 8; j += 4) {
            float4 c;
            c.x = acc[i][j + 0] + bv[j + 0];
            c.y = acc[i][j + 1] + bv[j + 1];
            c.z = acc[i][j + 2] + bv[j + 2];
            c.w = acc[i][j + 3] + bv[j + 3];
            if (ACT) {
                c.x = fmaxf(c.x, 0.f); c.y = fmaxf(c.y, 0.f);
                c.z = fmaxf(c.z, 0.f); c.w = fmaxf(c.w, 0.f);
            }
            *(float4*)(cp + j) = c;
        }
    }
}

// ============================ flash attention ===============================
// grid (S/64, B*H), block 256. Online-softmax over key tiles (only valid ones).
#define FP 68                       // smem pitch (floats)
#define FTS (64 * FP)               // one tile buffer
#define FLASH_SMEM (3 * FTS * 4)    // Qs, Ks(/Ps), Vs

__global__ __launch_bounds__(256)
void flash_attn_kernel(const float* __restrict__ qkv, float* __restrict__ ctx,
                       const int* __restrict__ dlen) {
    extern __shared__ float sm[];
    float* Qs = sm;
    float* Ks = sm + FTS;
    float* Vs = sm + 2 * FTS;
    float* Ps = Ks;                 // alias (Ks dead after S computed)

    const int qt = blockIdx.x;
    const int bh = blockIdx.y;
    const int b  = bh >> 3;
    const int h  = bh & 7;
    const int len = dlen[b];
    const int nk = (len + 63) >> 6;

    const int tid = threadIdx.x;
    const int tx = tid & 15;
    const int ty = tid >> 4;
    const int ty4 = ty * 4;

    const float* qbase = qkv + (size_t)b * Sn * 1536 + h * 64;
    const float* kbase = qbase + 512;
    const float* vbase = qbase + 1024;

    // load Q tile (scaled)
    const float scale = 0.125f;     // 1/sqrt(64)
#pragma unroll
    for (int u = 0; u < 4; u++) {
        int f = tid + u * 256;
        int r = f >> 4;
        int c = (f & 15) << 2;
        float4 v = *(const float4*)(qbase + (size_t)(qt * 64 + r) * 1536 + c);
        v.x *= scale; v.y *= scale; v.z *= scale; v.w *= scale;
        *(float4*)(Qs + r * FP + c) = v;
    }

    float m[4], l[4], O[4][4];
#pragma unroll
    for (int i = 0; i < 4; i++) {
        m[i] = -1e30f; l[i] = 0.f;
#pragma unroll
        for (int j = 0; j < 4; j++) O[i][j] = 0.f;
    }

    for (int kt = 0; kt < nk; kt++) {
        __syncthreads();            // previous iter's Ps/Vs reads done
#pragma unroll
        for (int u = 0; u < 4; u++) {
            int f = tid + u * 256;
            int r = f >> 4;
            int c = (f & 15) << 2;
            size_t grow = (size_t)(kt * 64 + r) * 1536;
            *(float4*)(Ks + r * FP + c) = *(const float4*)(kbase + grow + c);
            *(float4*)(Vs + r * FP + c) = *(const float4*)(vbase + grow + c);
        }
        __syncthreads();

        float Sv[4][4];
#pragma unroll
        for (int i = 0; i < 4; i++)
#pragma unroll
            for (int j = 0; j < 4; j++) Sv[i][j] = 0.f;

#pragma unroll 8
        for (int d = 0; d < 64; d++) {
            float av[4], bv[4];
#pragma unroll
            for (int i = 0; i < 4; i++) av[i] = Qs[(ty4 + i) * FP + d];
#pragma unroll
            for (int j = 0; j < 4; j++) bv[j] = Ks[(tx + 16 * j) * FP + d];
#pragma unroll
            for (int i = 0; i < 4; i++)
#pragma unroll
                for (int j = 0; j < 4; j++) Sv[i][j] += av[i] * bv[j];
        }

        // key-validity mask
#pragma unroll
        for (int j = 0; j < 4; j++) {
            int kg = kt * 64 + tx + 16 * j;
            if (kg >= len) {
#pragma unroll
                for (int i = 0; i < 4; i++) Sv[i][j] = -1e30f;
            }
        }

        // online softmax
        float alpha[4];
#pragma unroll
        for (int i = 0; i < 4; i++) {
            float mt = fmaxf(fmaxf(Sv[i][0], Sv[i][1]), fmaxf(Sv[i][2], Sv[i][3]));
#pragma unroll
            for (int o = 8; o; o >>= 1) mt = fmaxf(mt, __shfl_xor_sync(0xffffffffu, mt, o));
            float mn = fmaxf(m[i], mt);
            alpha[i] = expf(m[i] - mn);
            float rs = 0.f;
#pragma unroll
            for (int j = 0; j < 4; j++) {
                float p = expf(Sv[i][j] - mn);
                Sv[i][j] = p;
                rs += p;
            }
#pragma unroll
            for (int o = 8; o; o >>= 1) rs += __shfl_xor_sync(0xffffffffu, rs, o);
            l[i] = l[i] * alpha[i] + rs;
            m[i] = mn;
#pragma unroll
            for (int j = 0; j < 4; j++) O[i][j] *= alpha[i];
        }

        __syncthreads();            // all Ks reads done before Ps overwrite
#pragma unroll
        for (int i = 0; i < 4; i++)
#pragma unroll
            for (int j = 0; j < 4; j++) Ps[(ty4 + i) * FP + tx + 16 * j] = Sv[i][j];
        __syncthreads();

#pragma unroll 8
        for (int k = 0; k < 64; k++) {
            float pv[4], vv[4];
#pragma unroll
            for (int i = 0; i < 4; i++) pv[i] = Ps[(ty4 + i) * FP + k];
#pragma unroll
            for (int j = 0; j < 4; j++) vv[j] = Vs[k * FP + tx + 16 * j];
#pragma unroll
            for (int i = 0; i < 4; i++)
#pragma unroll
                for (int j = 0; j < 4; j++) O[i][j] += pv[i] * vv[j];
        }
    }

#pragma unroll
    for (int i = 0; i < 4; i++) {
        float inv = 1.f / l[i];
        size_t row = (size_t)(b * Sn + qt * 64 + ty4 + i);
        float* cp = ctx + row * 512 + h * 64;
#pragma unroll
        for (int j = 0; j < 4; j++) cp[tx + 16 * j] = O[i][j] * inv;
    }
}

// ============================ add + layernorm ===============================
__device__ __forceinline__ float blk_sum_128(float v, float* red) {
#pragma unroll
    for (int o = 16; o; o >>= 1) v += __shfl_xor_sync(0xffffffffu, v, o);
    __syncthreads();
    if ((threadIdx.x & 31) == 0) red[threadIdx.x >> 5] = v;
    __syncthreads();
    return red[0] + red[1] + red[2] + red[3];
}

__global__ __launch_bounds__(128)
void add_ln_kernel(float* __restrict__ x, const float* __restrict__ hh,
                   const float* __restrict__ g, const float* __restrict__ be) {
    __shared__ float red[4];
    int row = blockIdx.x;
    int t = threadIdx.x;
    size_t off = (size_t)row * 512 + t * 4;
    float4 xv = *(float4*)(x + off);
    float4 hv = *(const float4*)(hh + off);
    float v0 = xv.x + hv.x, v1 = xv.y + hv.y, v2 = xv.z + hv.z, v3 = xv.w + hv.w;
    float mean = blk_sum_128(v0 + v1 + v2 + v3, red) * (1.f / 512.f);
    float d0 = v0 - mean, d1 = v1 - mean, d2 = v2 - mean, d3 = v3 - mean;
    float var = blk_sum_128(d0 * d0 + d1 * d1 + d2 * d2 + d3 * d3, red) * (1.f / 512.f);
    float rstd = rsqrtf(var + 1e-5f);
    float4 gv = *(const float4*)(g + t * 4);
    float4 bv = *(const float4*)(be + t * 4);
    float4 o;
    o.x = d0 * rstd * gv.x + bv.x;
    o.y = d1 * rstd * gv.y + bv.y;
    o.z = d2 * rstd * gv.z + bv.z;
    o.w = d3 * rstd * gv.w + bv.w;
    *(float4*)(x + off) = o;
}

// ============================ final head ====================================
// one warp per token: o = tanh(x@Wout + a[b]) @ Wcomb ; mask
__global__ __launch_bounds__(256)
void final_logits_kernel(const float* __restrict__ x, const float* __restrict__ addr,
                         const float* __restrict__ poi, const int* __restrict__ atype,
                         const float* __restrict__ Wa, const float* __restrict__ ba,
                         const float* __restrict__ Wout, const float* __restrict__ Wcomb,
                         const int* __restrict__ dlen, float* __restrict__ logits) {
    int warp = (blockIdx.x * blockDim.x + threadIdx.x) >> 5;
    int lane = threadIdx.x & 31;
    if (warp >= BSn) return;
    int b = warp >> 10;
    int s = warp & 1023;
    int t = atype[b];
    float aj = ba[lane]
             + addr[b]        * Wa[lane]
             + poi[t * 3 + 0] * Wa[32 + lane]
             + poi[t * 3 + 1] * Wa[64 + lane]
             + poi[t * 3 + 2] * Wa[96 + lane];
    const float* xr = x + (size_t)warp * 512;
    float acc = 0.f;
#pragma unroll 8
    for (int d = 0; d < 512; d++) acc += xr[d] * Wout[d * 32 + lane];
    float tv = tanhf(acc + aj) * Wcomb[lane];
#pragma unroll
    for (int o = 16; o; o >>= 1) tv += __shfl_xor_sync(0xffffffffu, tv, o);
    if (lane == 0) logits[warp] = (s < dlen[b]) ? tv : -1e9f;
}

__global__ __launch_bounds__(256)
void logsoftmax_kernel(const float* __restrict__ logits, const int* __restrict__ dlen,
                       float* __restrict__ out) {
    __shared__ float red[8];
    int b = blockIdx.x;
    int len = dlen[b];
    const float* lg = logits + (size_t)b * Sn;
    // max
    float mx = -1e30f;
    for (int s = threadIdx.x; s < len; s += 256) mx = fmaxf(mx, lg[s]);
#pragma unroll
    for (int o = 16; o; o >>= 1) mx = fmaxf(mx, __shfl_xor_sync(0xffffffffu, mx, o));
    if ((threadIdx.x & 31) == 0) red[threadIdx.x >> 5] = mx;
    __syncthreads();
    mx = red[0];
#pragma unroll
    for (int w = 1; w < 8; w++) mx = fmaxf(mx, red[w]);
    __syncthreads();
    // sum exp
    float sum = 0.f;
    for (int s = threadIdx.x; s < len; s += 256) sum += expf(lg[s] - mx);
#pragma unroll
    for (int o = 16; o; o >>= 1) sum += __shfl_xor_sync(0xffffffffu, sum, o);
    if ((threadIdx.x & 31) == 0) red[threadIdx.x >> 5] = sum;
    __syncthreads();
    sum = red[0] + red[1] + red[2] + red[3] + red[4] + red[5] + red[6] + red[7];
    float lse = logf(sum) + mx;
    for (int s = threadIdx.x; s < Sn; s += 256)
        out[(size_t)b * Sn + s] = (s < len) ? (lg[s] - lse) : 0.f;
}

// ============================ launch ========================================
extern "C" void kernel_launch(void* const* d_in, const int* in_sizes, int n_in,
                              void* d_out, int out_size) {
    const float* addr  = (const float*)d_in[0];
    const float* loc   = (const float*)d_in[1];
    const float* tdist = (const float*)d_in[2];
    const float* Wtd   = (const float*)d_in[3];
    const float* btd   = (const float*)d_in[4];
    const float* Wemb  = (const float*)d_in[5];
    const float* bemb  = (const float*)d_in[6];
    const float* Wqkv  = (const float*)d_in[7];
    const float* bqkv  = (const float*)d_in[8];
    const float* Wo    = (const float*)d_in[9];
    const float* bo    = (const float*)d_in[10];
    const float* ln1g  = (const float*)d_in[11];
    const float* ln1b  = (const float*)d_in[12];
    const float* W1    = (const float*)d_in[13];
    const float* b1    = (const float*)d_in[14];
    const float* W2    = (const float*)d_in[15];
    const float* b2    = (const float*)d_in[16];
    const float* ln2g  = (const float*)d_in[17];
    const float* ln2b  = (const float*)d_in[18];
    const float* poi   = (const float*)d_in[19];
    const float* Wa    = (const float*)d_in[20];
    const float* ba    = (const float*)d_in[21];
    const float* Wout  = (const float*)d_in[22];
    const float* Wcomb = (const float*)d_in[23];
    const int*   atype = (const int*)d_in[24];
    const int*   dlen  = (const int*)d_in[25];
    float* out = (float*)d_out;

    float *x, *qkvb, *ctx, *t1, *t2, *lg;
    cudaGetSymbolAddress((void**)&x,    g_x);
    cudaGetSymbolAddress((void**)&qkvb, g_qkv);
    cudaGetSymbolAddress((void**)&ctx,  g_ctx);
    cudaGetSymbolAddress((void**)&t1,   g_t1);
    cudaGetSymbolAddress((void**)&t2,   g_t2);
    cudaGetSymbolAddress((void**)&lg,   g_logits);

    cudaFuncSetAttribute(flash_attn_kernel,
                         cudaFuncAttributeMaxDynamicSharedMemorySize, FLASH_SMEM);

    embed_kernel<<<BSn, 128>>>(loc, tdist, Wtd, btd, Wemb, bemb, x);

    for (int l = 0; l < Ln; l++) {
        sgemm_bias<0><<<dim3(12, 256), 256>>>(x, Wqkv + (size_t)l * Dn * 3 * Dn,
                                              bqkv + l * 3 * Dn, qkvb, BSn, 3 * Dn, Dn);
        flash_attn_kernel<<<dim3(16, Bn * Hn), 256, FLASH_SMEM>>>(qkvb, ctx, dlen);
        sgemm_bias<0><<<dim3(4, 256), 256>>>(ctx, Wo + (size_t)l * Dn * Dn,
                                             bo + l * Dn, t1, BSn, Dn, Dn);
        add_ln_kernel<<<BSn, 128>>>(x, t1, ln1g + l * Dn, ln1b + l * Dn);
        sgemm_bias<1><<<dim3(4, 256), 256>>>(x, W1 + (size_t)l * Dn * Dn,
                                             b1 + l * Dn, t2, BSn, Dn, Dn);
        sgemm_bias<0><<<dim3(4, 256), 256>>>(t2, W2 + (size_t)l * Dn * Dn,
                                             b2 + l * Dn, t1, BSn, Dn, Dn);
        add_ln_kernel<<<BSn, 128>>>(x, t1, ln2g + l * Dn, ln2b + l * Dn);
    }

    final_logits_kernel<<<(BSn * 32) / 256, 256>>>(x, addr, poi, atype, Wa, ba,
                                                   Wout, Wcomb, dlen, lg);
    logsoftmax_kernel<<<Bn, 256>>>(lg, dlen, out);
}

// round 2
// speedup vs baseline: 1.6410x; 1.6410x over previous
#include <cuda_runtime.h>
#include <math.h>
#include <stdint.h>

#define Bn   32
#define Sn   1024
#define Dn   512
#define Hn   8
#define Ln   4
#define DHn  64
#define BSn  (Bn*Sn)
#define FCn  32

// ------------------------- scratch (device globals; no allocs allowed) ------
__device__ float g_x[(size_t)BSn * Dn];
__device__ float g_qkv[(size_t)BSn * 3 * Dn];
__device__ float g_ctx[(size_t)BSn * Dn];
__device__ float g_t1[(size_t)BSn * Dn];
__device__ float g_t2[(size_t)BSn * Dn];
__device__ float g_logits[BSn];

// ============================ embed =========================================
__global__ void embed_kernel(const float* __restrict__ loc,
                             const float* __restrict__ tdist,
                             const float* __restrict__ Wtd,
                             const float* __restrict__ btd,
                             const float* __restrict__ Wemb,
                             const float* __restrict__ bemb,
                             float* __restrict__ x) {
    int tok = blockIdx.x;
    const float* lp = loc + (size_t)tok * 16;
    const float* tp = tdist + (size_t)tok * 8;
    float in[19];
#pragma unroll
    for (int i = 0; i < 16; i++) in[i] = lp[i];
#pragma unroll
    for (int j = 0; j < 3; j++) {
        float s = btd[j];
#pragma unroll
        for (int i = 0; i < 8; i++) s += tp[i] * Wtd[i * 3 + j];
        in[16 + j] = s;
    }
    int d = threadIdx.x * 4;
    float4 acc = *(const float4*)(bemb + d);
#pragma unroll
    for (int i = 0; i < 19; i++) {
        float4 w = *(const float4*)(Wemb + i * 512 + d);
        float s = in[i];
        acc.x += s * w.x; acc.y += s * w.y; acc.z += s * w.z; acc.w += s * w.w;
    }
    *(float4*)(x + (size_t)tok * 512 + d) = acc;
}

// ============================ TF32 tensor-core GEMM =========================
// C[M,N] = act(A[M,K] @ W[K,N] + bias[N]); M%128==0, N%128==0, K%16==0.
// Block tile 128x128x16, 8 warps (2M x 4N), warp tile 64x32, mma.m16n8k8.tf32.

__device__ __forceinline__ float tf32r(float x) {
    unsigned u;
    asm("cvt.rna.tf32.f32 %0, %1;" : "=r"(u) : "f"(x));
    return __uint_as_float(u);
}

#define SPITCH 136

template <int ACT>
__global__ __launch_bounds__(256)
void tf32_gemm(const float* __restrict__ A, const float* __restrict__ W,
               const float* __restrict__ bias, float* __restrict__ C,
               int M, int N, int K) {
    __shared__ float As[16][SPITCH];   // [k][m], pitch 136 -> conflict-free frag loads
    __shared__ float Ws[16][SPITCH];   // [k][n]

    const int tid  = threadIdx.x;
    const int warp = tid >> 5;
    const int lane = tid & 31;
    const int wm = warp >> 2;          // 0..1
    const int wn = warp & 3;           // 0..3
    const int qid = lane >> 2;         // 0..7
    const int tq  = lane & 3;          // 0..3

    const int bm = blockIdx.y * 128;
    const int bn = blockIdx.x * 128;

    // global load mapping
    const int arow = tid >> 1;             // 0..127
    const int acol = (tid & 1) << 3;       // 0 or 8
    const int wrow = tid >> 4;             // 0..15
    const int wcol = (tid & 15) << 3;      // 0..120

    const float* Ap = A + (size_t)(bm + arow) * K + acol;
    const float* Wp = W + (size_t)wrow * N + bn + wcol;

    float4 ra0 = *(const float4*)(Ap);
    float4 ra1 = *(const float4*)(Ap + 4);
    float4 rw0 = *(const float4*)(Wp);
    float4 rw1 = *(const float4*)(Wp + 4);

    float acc[4][4][4];
#pragma unroll
    for (int i = 0; i < 4; i++)
#pragma unroll
        for (int j = 0; j < 4; j++)
#pragma unroll
            for (int c = 0; c < 4; c++) acc[i][j][c] = 0.f;

    for (int k0 = 0; k0 < K; k0 += 16) {
        // stage current chunk to smem (tf32-rounded)
        As[acol + 0][arow] = tf32r(ra0.x);
        As[acol + 1][arow] = tf32r(ra0.y);
        As[acol + 2][arow] = tf32r(ra0.z);
        As[acol + 3][arow] = tf32r(ra0.w);
        As[acol + 4][arow] = tf32r(ra1.x);
        As[acol + 5][arow] = tf32r(ra1.y);
        As[acol + 6][arow] = tf32r(ra1.z);
        As[acol + 7][arow] = tf32r(ra1.w);
        Ws[wrow][wcol + 0] = tf32r(rw0.x);
        Ws[wrow][wcol + 1] = tf32r(rw0.y);
        Ws[wrow][wcol + 2] = tf32r(rw0.z);
        Ws[wrow][wcol + 3] = tf32r(rw0.w);
        Ws[wrow][wcol + 4] = tf32r(rw1.x);
        Ws[wrow][wcol + 5] = tf32r(rw1.y);
        Ws[wrow][wcol + 6] = tf32r(rw1.z);
        Ws[wrow][wcol + 7] = tf32r(rw1.w);
        __syncthreads();

        // prefetch next chunk into registers
        if (k0 + 16 < K) {
            ra0 = *(const float4*)(Ap + k0 + 16);
            ra1 = *(const float4*)(Ap + k0 + 20);
            rw0 = *(const float4*)(Wp + (size_t)(k0 + 16) * N);
            rw1 = *(const float4*)(Wp + (size_t)(k0 + 16) * N + 4);
        }

#pragma unroll
        for (int kk = 0; kk < 16; kk += 8) {
            unsigned a[4][4], b[4][2];
#pragma unroll
            for (int am = 0; am < 4; am++) {
                int m0 = wm * 64 + am * 16;
                a[am][0] = __float_as_uint(As[kk + tq][m0 + qid]);
                a[am][1] = __float_as_uint(As[kk + tq][m0 + qid + 8]);
                a[am][2] = __float_as_uint(As[kk + tq + 4][m0 + qid]);
                a[am][3] = __float_as_uint(As[kk + tq + 4][m0 + qid + 8]);
            }
#pragma unroll
            for (int an = 0; an < 4; an++) {
                int n0 = wn * 32 + an * 8;
                b[an][0] = __float_as_uint(Ws[kk + tq][n0 + qid]);
                b[an][1] = __float_as_uint(Ws[kk + tq + 4][n0 + qid]);
            }
#pragma unroll
            for (int am = 0; am < 4; am++)
#pragma unroll
                for (int an = 0; an < 4; an++) {
                    asm volatile(
                        "mma.sync.aligned.m16n8k8.row.col.f32.tf32.tf32.f32 "
                        "{%0,%1,%2,%3}, {%4,%5,%6,%7}, {%8,%9}, {%0,%1,%2,%3};"
                        : "+f"(acc[am][an][0]), "+f"(acc[am][an][1]),
                          "+f"(acc[am][an][2]), "+f"(acc[am][an][3])
                        : "r"(a[am][0]), "r"(a[am][1]), "r"(a[am][2]), "r"(a[am][3]),
                          "r"(b[an][0]), "r"(b[an][1]));
                }
        }
        __syncthreads();
    }

    // epilogue
#pragma unroll
    for (int am = 0; am < 4; am++) {
        int r0 = bm + wm * 64 + am * 16 + qid;
#pragma unroll
        for (int an = 0; an < 4; an++) {
            int col = bn + wn * 32 + an * 8 + 2 * tq;
            float b0 = bias[col], b1 = bias[col + 1];
            float v0 = acc[am][an][0] + b0;
            float v1 = acc[am][an][1] + b1;
            float v2 = acc[am][an][2] + b0;
            float v3 = acc[am][an][3] + b1;
            if (ACT) {
                v0 = fmaxf(v0, 0.f); v1 = fmaxf(v1, 0.f);
                v2 = fmaxf(v2, 0.f); v3 = fmaxf(v3, 0.f);
            }
            *(float2*)(C + (size_t)r0 * N + col)       = make_float2(v0, v1);
            *(float2*)(C + (size_t)(r0 + 8) * N + col) = make_float2(v2, v3);
        }
    }
}

// ============================ flash attention ===============================
#define FP 68
#define FTS (64 * FP)
#define FLASH_SMEM (3 * FTS * 4)

__global__ __launch_bounds__(256)
void flash_attn_kernel(const float* __restrict__ qkv, float* __restrict__ ctx,
                       const int* __restrict__ dlen) {
    extern __shared__ float sm[];
    float* Qs = sm;
    float* Ks = sm + FTS;
    float* Vs = sm + 2 * FTS;
    float* Ps = Ks;

    const int qt = blockIdx.x;
    const int bh = blockIdx.y;
    const int b  = bh >> 3;
    const int h  = bh & 7;
    const int len = dlen[b];
    const int nk = (len + 63) >> 6;

    const int tid = threadIdx.x;
    const int tx = tid & 15;
    const int ty = tid >> 4;
    const int ty4 = ty * 4;

    const float* qbase = qkv + (size_t)b * Sn * 1536 + h * 64;
    const float* kbase = qbase + 512;
    const float* vbase = qbase + 1024;

    const float scale = 0.125f;
#pragma unroll
    for (int u = 0; u < 4; u++) {
        int f = tid + u * 256;
        int r = f >> 4;
        int c = (f & 15) << 2;
        float4 v = *(const float4*)(qbase + (size_t)(qt * 64 + r) * 1536 + c);
        v.x *= scale; v.y *= scale; v.z *= scale; v.w *= scale;
        *(float4*)(Qs + r * FP + c) = v;
    }

    float m[4], l[4], O[4][4];
#pragma unroll
    for (int i = 0; i < 4; i++) {
        m[i] = -1e30f; l[i] = 0.f;
#pragma unroll
        for (int j = 0; j < 4; j++) O[i][j] = 0.f;
    }

    for (int kt = 0; kt < nk; kt++) {
        __syncthreads();
#pragma unroll
        for (int u = 0; u < 4; u++) {
            int f = tid + u * 256;
            int r = f >> 4;
            int c = (f & 15) << 2;
            size_t grow = (size_t)(kt * 64 + r) * 1536;
            *(float4*)(Ks + r * FP + c) = *(const float4*)(kbase + grow + c);
            *(float4*)(Vs + r * FP + c) = *(const float4*)(vbase + grow + c);
        }
        __syncthreads();

        float Sv[4][4];
#pragma unroll
        for (int i = 0; i < 4; i++)
#pragma unroll
            for (int j = 0; j < 4; j++) Sv[i][j] = 0.f;

#pragma unroll 8
        for (int d = 0; d < 64; d++) {
            float av[4], bv[4];
#pragma unroll
            for (int i = 0; i < 4; i++) av[i] = Qs[(ty4 + i) * FP + d];
#pragma unroll
            for (int j = 0; j < 4; j++) bv[j] = Ks[(tx + 16 * j) * FP + d];
#pragma unroll
            for (int i = 0; i < 4; i++)
#pragma unroll
                for (int j = 0; j < 4; j++) Sv[i][j] += av[i] * bv[j];
        }

#pragma unroll
        for (int j = 0; j < 4; j++) {
            int kg = kt * 64 + tx + 16 * j;
            if (kg >= len) {
#pragma unroll
                for (int i = 0; i < 4; i++) Sv[i][j] = -1e30f;
            }
        }

        float alpha[4];
#pragma unroll
        for (int i = 0; i < 4; i++) {
            float mt = fmaxf(fmaxf(Sv[i][0], Sv[i][1]), fmaxf(Sv[i][2], Sv[i][3]));
#pragma unroll
            for (int o = 8; o; o >>= 1) mt = fmaxf(mt, __shfl_xor_sync(0xffffffffu, mt, o));
            float mn = fmaxf(m[i], mt);
            alpha[i] = expf(m[i] - mn);
            float rs = 0.f;
#pragma unroll
            for (int j = 0; j < 4; j++) {
                float p = expf(Sv[i][j] - mn);
                Sv[i][j] = p;
                rs += p;
            }
#pragma unroll
            for (int o = 8; o; o >>= 1) rs += __shfl_xor_sync(0xffffffffu, rs, o);
            l[i] = l[i] * alpha[i] + rs;
            m[i] = mn;
#pragma unroll
            for (int j = 0; j < 4; j++) O[i][j] *= alpha[i];
        }

        __syncthreads();
#pragma unroll
        for (int i = 0; i < 4; i++)
#pragma unroll
            for (int j = 0; j < 4; j++) Ps[(ty4 + i) * FP + tx + 16 * j] = Sv[i][j];
        __syncthreads();

#pragma unroll 8
        for (int k = 0; k < 64; k++) {
            float pv[4], vv[4];
#pragma unroll
            for (int i = 0; i < 4; i++) pv[i] = Ps[(ty4 + i) * FP + k];
#pragma unroll
            for (int j = 0; j < 4; j++) vv[j] = Vs[k * FP + tx + 16 * j];
#pragma unroll
            for (int i = 0; i < 4; i++)
#pragma unroll
                for (int j = 0; j < 4; j++) O[i][j] += pv[i] * vv[j];
        }
    }

#pragma unroll
    for (int i = 0; i < 4; i++) {
        float inv = 1.f / l[i];
        size_t row = (size_t)(b * Sn + qt * 64 + ty4 + i);
        float* cp = ctx + row * 512 + h * 64;
#pragma unroll
        for (int j = 0; j < 4; j++) cp[tx + 16 * j] = O[i][j] * inv;
    }
}

// ============================ add + layernorm ===============================
__device__ __forceinline__ float blk_sum_128(float v, float* red) {
#pragma unroll
    for (int o = 16; o; o >>= 1) v += __shfl_xor_sync(0xffffffffu, v, o);
    __syncthreads();
    if ((threadIdx.x & 31) == 0) red[threadIdx.x >> 5] = v;
    __syncthreads();
    return red[0] + red[1] + red[2] + red[3];
}

__global__ __launch_bounds__(128)
void add_ln_kernel(float* __restrict__ x, const float* __restrict__ hh,
                   const float* __restrict__ g, const float* __restrict__ be) {
    __shared__ float red[4];
    int row = blockIdx.x;
    int t = threadIdx.x;
    size_t off = (size_t)row * 512 + t * 4;
    float4 xv = *(float4*)(x + off);
    float4 hv = *(const float4*)(hh + off);
    float v0 = xv.x + hv.x, v1 = xv.y + hv.y, v2 = xv.z + hv.z, v3 = xv.w + hv.w;
    float mean = blk_sum_128(v0 + v1 + v2 + v3, red) * (1.f / 512.f);
    float d0 = v0 - mean, d1 = v1 - mean, d2 = v2 - mean, d3 = v3 - mean;
    float var = blk_sum_128(d0 * d0 + d1 * d1 + d2 * d2 + d3 * d3, red) * (1.f / 512.f);
    float rstd = rsqrtf(var + 1e-5f);
    float4 gv = *(const float4*)(g + t * 4);
    float4 bv = *(const float4*)(be + t * 4);
    float4 o;
    o.x = d0 * rstd * gv.x + bv.x;
    o.y = d1 * rstd * gv.y + bv.y;
    o.z = d2 * rstd * gv.z + bv.z;
    o.w = d3 * rstd * gv.w + bv.w;
    *(float4*)(x + off) = o;
}

// ============================ final head ====================================
__global__ __launch_bounds__(256)
void final_logits_kernel(const float* __restrict__ x, const float* __restrict__ addr,
                         const float* __restrict__ poi, const int* __restrict__ atype,
                         const float* __restrict__ Wa, const float* __restrict__ ba,
                         const float* __restrict__ Wout, const float* __restrict__ Wcomb,
                         const int* __restrict__ dlen, float* __restrict__ logits) {
    int warp = (blockIdx.x * blockDim.x + threadIdx.x) >> 5;
    int lane = threadIdx.x & 31;
    if (warp >= BSn) return;
    int b = warp >> 10;
    int s = warp & 1023;
    int t = atype[b];
    float aj = ba[lane]
             + addr[b]        * Wa[lane]
             + poi[t * 3 + 0] * Wa[32 + lane]
             + poi[t * 3 + 1] * Wa[64 + lane]
             + poi[t * 3 + 2] * Wa[96 + lane];
    const float* xr = x + (size_t)warp * 512;
    float acc = 0.f;
#pragma unroll 8
    for (int d = 0; d < 512; d++) acc += xr[d] * Wout[d * 32 + lane];
    float tv = tanhf(acc + aj) * Wcomb[lane];
#pragma unroll
    for (int o = 16; o; o >>= 1) tv += __shfl_xor_sync(0xffffffffu, tv, o);
    if (lane == 0) logits[warp] = (s < dlen[b]) ? tv : -1e9f;
}

__global__ __launch_bounds__(256)
void logsoftmax_kernel(const float* __restrict__ logits, const int* __restrict__ dlen,
                       float* __restrict__ out) {
    __shared__ float red[8];
    int b = blockIdx.x;
    int len = dlen[b];
    const float* lg = logits + (size_t)b * Sn;
    float mx = -1e30f;
    for (int s = threadIdx.x; s < len; s += 256) mx = fmaxf(mx, lg[s]);
#pragma unroll
    for (int o = 16; o; o >>= 1) mx = fmaxf(mx, __shfl_xor_sync(0xffffffffu, mx, o));
    if ((threadIdx.x & 31) == 0) red[threadIdx.x >> 5] = mx;
    __syncthreads();
    mx = red[0];
#pragma unroll
    for (int w = 1; w < 8; w++) mx = fmaxf(mx, red[w]);
    __syncthreads();
    float sum = 0.f;
    for (int s = threadIdx.x; s < len; s += 256) sum += expf(lg[s] - mx);
#pragma unroll
    for (int o = 16; o; o >>= 1) sum += __shfl_xor_sync(0xffffffffu, sum, o);
    if ((threadIdx.x & 31) == 0) red[threadIdx.x >> 5] = sum;
    __syncthreads();
    sum = red[0] + red[1] + red[2] + red[3] + red[4] + red[5] + red[6] + red[7];
    float lse = logf(sum) + mx;
    for (int s = threadIdx.x; s < Sn; s += 256)
        out[(size_t)b * Sn + s] = (s < len) ? (lg[s] - lse) : 0.f;
}

// ============================ launch ========================================
extern "C" void kernel_launch(void* const* d_in, const int* in_sizes, int n_in,
                              void* d_out, int out_size) {
    const float* addr  = (const float*)d_in[0];
    const float* loc   = (const float*)d_in[1];
    const float* tdist = (const float*)d_in[2];
    const float* Wtd   = (const float*)d_in[3];
    const float* btd   = (const float*)d_in[4];
    const float* Wemb  = (const float*)d_in[5];
    const float* bemb  = (const float*)d_in[6];
    const float* Wqkv  = (const float*)d_in[7];
    const float* bqkv  = (const float*)d_in[8];
    const float* Wo    = (const float*)d_in[9];
    const float* bo    = (const float*)d_in[10];
    const float* ln1g  = (const float*)d_in[11];
    const float* ln1b  = (const float*)d_in[12];
    const float* W1    = (const float*)d_in[13];
    const float* b1    = (const float*)d_in[14];
    const float* W2    = (const float*)d_in[15];
    const float* b2    = (const float*)d_in[16];
    const float* ln2g  = (const float*)d_in[17];
    const float* ln2b  = (const float*)d_in[18];
    const float* poi   = (const float*)d_in[19];
    const float* Wa    = (const float*)d_in[20];
    const float* ba    = (const float*)d_in[21];
    const float* Wout  = (const float*)d_in[22];
    const float* Wcomb = (const float*)d_in[23];
    const int*   atype = (const int*)d_in[24];
    const int*   dlen  = (const int*)d_in[25];
    float* out = (float*)d_out;

    float *x, *qkvb, *ctx, *t1, *t2, *lg;
    cudaGetSymbolAddress((void**)&x,    g_x);
    cudaGetSymbolAddress((void**)&qkvb, g_qkv);
    cudaGetSymbolAddress((void**)&ctx,  g_ctx);
    cudaGetSymbolAddress((void**)&t1,   g_t1);
    cudaGetSymbolAddress((void**)&t2,   g_t2);
    cudaGetSymbolAddress((void**)&lg,   g_logits);

    cudaFuncSetAttribute(flash_attn_kernel,
                         cudaFuncAttributeMaxDynamicSharedMemorySize, FLASH_SMEM);

    embed_kernel<<<BSn, 128>>>(loc, tdist, Wtd, btd, Wemb, bemb, x);

    for (int l = 0; l < Ln; l++) {
        tf32_gemm<0><<<dim3(12, 256), 256>>>(x, Wqkv + (size_t)l * Dn * 3 * Dn,
                                             bqkv + l * 3 * Dn, qkvb, BSn, 3 * Dn, Dn);
        flash_attn_kernel<<<dim3(16, Bn * Hn), 256, FLASH_SMEM>>>(qkvb, ctx, dlen);
        tf32_gemm<0><<<dim3(4, 256), 256>>>(ctx, Wo + (size_t)l * Dn * Dn,
                                            bo + l * Dn, t1, BSn, Dn, Dn);
        add_ln_kernel<<<BSn, 128>>>(x, t1, ln1g + l * Dn, ln1b + l * Dn);
        tf32_gemm<1><<<dim3(4, 256), 256>>>(x, W1 + (size_t)l * Dn * Dn,
                                            b1 + l * Dn, t2, BSn, Dn, Dn);
        tf32_gemm<0><<<dim3(4, 256), 256>>>(t2, W2 + (size_t)l * Dn * Dn,
                                            b2 + l * Dn, t1, BSn, Dn, Dn);
        add_ln_kernel<<<BSn, 128>>>(x, t1, ln2g + l * Dn, ln2b + l * Dn);
    }

    final_logits_kernel<<<(BSn * 32) / 256, 256>>>(x, addr, poi, atype, Wa, ba,
                                                   Wout, Wcomb, dlen, lg);
    logsoftmax_kernel<<<Bn, 256>>>(lg, dlen, out);
}

// round 4
// speedup vs baseline: 2.4847x; 1.5142x over previous
#include <cuda_runtime.h>
#include <math.h>
#include <stdint.h>

#define Bn   32
#define Sn   1024
#define Dn   512
#define Hn   8
#define Ln   4
#define DHn  64
#define BSn  (Bn*Sn)
#define FCn  32

// ------------------------- scratch (device globals; no allocs allowed) ------
__device__ float g_x[(size_t)BSn * Dn];
__device__ float g_qkv[(size_t)BSn * 3 * Dn];
__device__ float g_ctx[(size_t)BSn * Dn];
__device__ float g_t1[(size_t)BSn * Dn];
__device__ float g_t2[(size_t)BSn * Dn];
__device__ float g_logits[BSn];

__device__ __forceinline__ float tf32r(float x) {
    unsigned u;
    asm("cvt.rna.tf32.f32 %0, %1;" : "=r"(u) : "f"(x));
    return __uint_as_float(u);
}

// ============================ embed =========================================
__global__ void embed_kernel(const float* __restrict__ loc,
                             const float* __restrict__ tdist,
                             const float* __restrict__ Wtd,
                             const float* __restrict__ btd,
                             const float* __restrict__ Wemb,
                             const float* __restrict__ bemb,
                             float* __restrict__ x) {
    int tok = blockIdx.x;
    const float* lp = loc + (size_t)tok * 16;
    const float* tp = tdist + (size_t)tok * 8;
    float in[19];
#pragma unroll
    for (int i = 0; i < 16; i++) in[i] = lp[i];
#pragma unroll
    for (int j = 0; j < 3; j++) {
        float s = btd[j];
#pragma unroll
        for (int i = 0; i < 8; i++) s += tp[i] * Wtd[i * 3 + j];
        in[16 + j] = s;
    }
    int d = threadIdx.x * 4;
    float4 acc = *(const float4*)(bemb + d);
#pragma unroll
    for (int i = 0; i < 19; i++) {
        float4 w = *(const float4*)(Wemb + i * 512 + d);
        float s = in[i];
        acc.x += s * w.x; acc.y += s * w.y; acc.z += s * w.z; acc.w += s * w.w;
    }
    *(float4*)(x + (size_t)tok * 512 + d) = acc;
}

// ============================ TF32 tensor-core GEMM =========================
#define SPITCH 136

template <int ACT>
__global__ __launch_bounds__(256)
void tf32_gemm(const float* __restrict__ A, const float* __restrict__ W,
               const float* __restrict__ bias, float* __restrict__ C,
               int M, int N, int K) {
    __shared__ float As[16][SPITCH];
    __shared__ float Ws[16][SPITCH];

    const int tid  = threadIdx.x;
    const int warp = tid >> 5;
    const int lane = tid & 31;
    const int wm = warp >> 2;
    const int wn = warp & 3;
    const int qid = lane >> 2;
    const int tq  = lane & 3;

    const int bm = blockIdx.y * 128;
    const int bn = blockIdx.x * 128;

    const int arow = tid >> 1;
    const int acol = (tid & 1) << 3;
    const int wrow = tid >> 4;
    const int wcol = (tid & 15) << 3;

    const float* Ap = A + (size_t)(bm + arow) * K + acol;
    const float* Wp = W + (size_t)wrow * N + bn + wcol;

    float4 ra0 = *(const float4*)(Ap);
    float4 ra1 = *(const float4*)(Ap + 4);
    float4 rw0 = *(const float4*)(Wp);
    float4 rw1 = *(const float4*)(Wp + 4);

    float acc[4][4][4];
#pragma unroll
    for (int i = 0; i < 4; i++)
#pragma unroll
        for (int j = 0; j < 4; j++)
#pragma unroll
            for (int c = 0; c < 4; c++) acc[i][j][c] = 0.f;

    for (int k0 = 0; k0 < K; k0 += 16) {
        As[acol + 0][arow] = tf32r(ra0.x);
        As[acol + 1][arow] = tf32r(ra0.y);
        As[acol + 2][arow] = tf32r(ra0.z);
        As[acol + 3][arow] = tf32r(ra0.w);
        As[acol + 4][arow] = tf32r(ra1.x);
        As[acol + 5][arow] = tf32r(ra1.y);
        As[acol + 6][arow] = tf32r(ra1.z);
        As[acol + 7][arow] = tf32r(ra1.w);
        Ws[wrow][wcol + 0] = tf32r(rw0.x);
        Ws[wrow][wcol + 1] = tf32r(rw0.y);
        Ws[wrow][wcol + 2] = tf32r(rw0.z);
        Ws[wrow][wcol + 3] = tf32r(rw0.w);
        Ws[wrow][wcol + 4] = tf32r(rw1.x);
        Ws[wrow][wcol + 5] = tf32r(rw1.y);
        Ws[wrow][wcol + 6] = tf32r(rw1.z);
        Ws[wrow][wcol + 7] = tf32r(rw1.w);
        __syncthreads();

        if (k0 + 16 < K) {
            ra0 = *(const float4*)(Ap + k0 + 16);
            ra1 = *(const float4*)(Ap + k0 + 20);
            rw0 = *(const float4*)(Wp + (size_t)(k0 + 16) * N);
            rw1 = *(const float4*)(Wp + (size_t)(k0 + 16) * N + 4);
        }

#pragma unroll
        for (int kk = 0; kk < 16; kk += 8) {
            unsigned a[4][4], b[4][2];
#pragma unroll
            for (int am = 0; am < 4; am++) {
                int m0 = wm * 64 + am * 16;
                a[am][0] = __float_as_uint(As[kk + tq][m0 + qid]);
                a[am][1] = __float_as_uint(As[kk + tq][m0 + qid + 8]);
                a[am][2] = __float_as_uint(As[kk + tq + 4][m0 + qid]);
                a[am][3] = __float_as_uint(As[kk + tq + 4][m0 + qid + 8]);
            }
#pragma unroll
            for (int an = 0; an < 4; an++) {
                int n0 = wn * 32 + an * 8;
                b[an][0] = __float_as_uint(Ws[kk + tq][n0 + qid]);
                b[an][1] = __float_as_uint(Ws[kk + tq + 4][n0 + qid]);
            }
#pragma unroll
            for (int am = 0; am < 4; am++)
#pragma unroll
                for (int an = 0; an < 4; an++) {
                    asm volatile(
                        "mma.sync.aligned.m16n8k8.row.col.f32.tf32.tf32.f32 "
                        "{%0,%1,%2,%3}, {%4,%5,%6,%7}, {%8,%9}, {%0,%1,%2,%3};"
                        : "+f"(acc[am][an][0]), "+f"(acc[am][an][1]),
                          "+f"(acc[am][an][2]), "+f"(acc[am][an][3])
                        : "r"(a[am][0]), "r"(a[am][1]), "r"(a[am][2]), "r"(a[am][3]),
                          "r"(b[an][0]), "r"(b[an][1]));
                }
        }
        __syncthreads();
    }

#pragma unroll
    for (int am = 0; am < 4; am++) {
        int r0 = bm + wm * 64 + am * 16 + qid;
#pragma unroll
        for (int an = 0; an < 4; an++) {
            int col = bn + wn * 32 + an * 8 + 2 * tq;
            float b0 = bias[col], b1 = bias[col + 1];
            float v0 = acc[am][an][0] + b0;
            float v1 = acc[am][an][1] + b1;
            float v2 = acc[am][an][2] + b0;
            float v3 = acc[am][an][3] + b1;
            if (ACT) {
                v0 = fmaxf(v0, 0.f); v1 = fmaxf(v1, 0.f);
                v2 = fmaxf(v2, 0.f); v3 = fmaxf(v3, 0.f);
            }
            *(float2*)(C + (size_t)r0 * N + col)       = make_float2(v0, v1);
            *(float2*)(C + (size_t)(r0 + 8) * N + col) = make_float2(v2, v3);
        }
    }
}

// ============================ flash attention (TF32 mma) ====================
// block 128 thr (4 warps), 64 q-rows per block, warp tile m=16.
// Ks [64][68]: S-phase B-frag loads conflict-free (bank=4*qid+tq)
// Vs [64][72]: PV-phase B-frag loads conflict-free (bank=8(tq+n)+qid)
// Qs [64][68]: staging for Q frags, then reused as per-warp P tiles.
#define KP 68
#define VP 72
#define FLASH_SMEM ((64 * KP + 64 * VP + 64 * KP) * 4)

#define MMA_TF32(C0,C1,C2,C3,A0,A1,A2,A3,B0,B1)                              \
    asm volatile(                                                            \
        "mma.sync.aligned.m16n8k8.row.col.f32.tf32.tf32.f32 "                \
        "{%0,%1,%2,%3}, {%4,%5,%6,%7}, {%8,%9}, {%0,%1,%2,%3};"              \
        : "+f"(C0), "+f"(C1), "+f"(C2), "+f"(C3)                             \
        : "r"(A0), "r"(A1), "r"(A2), "r"(A3), "r"(B0), "r"(B1))

__global__ __launch_bounds__(128)
void flash_mma_kernel(const float* __restrict__ qkv, float* __restrict__ ctx,
                      const int* __restrict__ dlen) {
    extern __shared__ float sm[];
    float* Ks = sm;                       // [64][KP]
    float* Vs = sm + 64 * KP;             // [64][VP]
    float* Qs = sm + 64 * KP + 64 * VP;   // [64][KP] -> later P

    const int qt = blockIdx.x;
    const int bh = blockIdx.y;
    const int b  = bh >> 3;
    const int h  = bh & 7;
    const int len = dlen[b];
    const int nk = (len + 63) >> 6;

    const int tid = threadIdx.x;
    const int warp = tid >> 5;
    const int lane = tid & 31;
    const int qid = lane >> 2;
    const int tq  = lane & 3;
    const int m0  = warp * 16;

    const float* qbase = qkv + (size_t)b * Sn * 1536 + h * 64;
    const float* kbase = qbase + 512;
    const float* vbase = qbase + 1024;

    // ---- load Q tile (scaled, tf32-rounded) ----
    {
        const float scale = 0.125f;
#pragma unroll
        for (int u = 0; u < 8; u++) {
            int f = tid + u * 128;
            int r = f >> 4, c = (f & 15) << 2;
            float4 v = *(const float4*)(qbase + (size_t)(qt * 64 + r) * 1536 + c);
            v.x = tf32r(v.x * scale); v.y = tf32r(v.y * scale);
            v.z = tf32r(v.z * scale); v.w = tf32r(v.w * scale);
            *(float4*)(Qs + r * KP + c) = v;
        }
    }
    __syncthreads();

    // ---- Q register fragments (8 k-steps) ----
    unsigned aq[8][4];
#pragma unroll
    for (int k8 = 0; k8 < 8; k8++) {
        int k = k8 * 8;
        aq[k8][0] = __float_as_uint(Qs[(m0 + qid) * KP + k + tq]);
        aq[k8][1] = __float_as_uint(Qs[(m0 + qid + 8) * KP + k + tq]);
        aq[k8][2] = __float_as_uint(Qs[(m0 + qid) * KP + k + tq + 4]);
        aq[k8][3] = __float_as_uint(Qs[(m0 + qid + 8) * KP + k + tq + 4]);
    }
    __syncthreads();            // Qs now dead -> reuse as P

    float* Pw = Qs + m0 * KP;   // per-warp P tile [16][KP]

    float mr0 = -1e30f, mr1 = -1e30f, lr0 = 0.f, lr1 = 0.f;
    float O[8][4];
#pragma unroll
    for (int n = 0; n < 8; n++)
#pragma unroll
        for (int c = 0; c < 4; c++) O[n][c] = 0.f;

    for (int kt = 0; kt < nk; kt++) {
        __syncthreads();
#pragma unroll
        for (int u = 0; u < 8; u++) {
            int f = tid + u * 128;
            int r = f >> 4, c = (f & 15) << 2;
            size_t grow = (size_t)(kt * 64 + r) * 1536;
            float4 kv = *(const float4*)(kbase + grow + c);
            float4 vv = *(const float4*)(vbase + grow + c);
            kv.x = tf32r(kv.x); kv.y = tf32r(kv.y);
            kv.z = tf32r(kv.z); kv.w = tf32r(kv.w);
            vv.x = tf32r(vv.x); vv.y = tf32r(vv.y);
            vv.z = tf32r(vv.z); vv.w = tf32r(vv.w);
            *(float4*)(Ks + r * KP + c) = kv;
            *(float4*)(Vs + r * VP + c) = vv;
        }
        __syncthreads();

        // ---- S = Q @ K^T ----
        float c[8][4];
#pragma unroll
        for (int n = 0; n < 8; n++)
#pragma unroll
            for (int j = 0; j < 4; j++) c[n][j] = 0.f;

#pragma unroll
        for (int k8 = 0; k8 < 8; k8++) {
            int k = k8 * 8;
#pragma unroll
            for (int n = 0; n < 8; n++) {
                unsigned b0 = __float_as_uint(Ks[(n * 8 + qid) * KP + k + tq]);
                unsigned b1 = __float_as_uint(Ks[(n * 8 + qid) * KP + k + tq + 4]);
                MMA_TF32(c[n][0], c[n][1], c[n][2], c[n][3],
                         aq[k8][0], aq[k8][1], aq[k8][2], aq[k8][3], b0, b1);
            }
        }

        // ---- mask + online softmax ----
        const int cb = kt * 64 + 2 * tq;
        float mx0 = -1e30f, mx1 = -1e30f;
#pragma unroll
        for (int n = 0; n < 8; n++) {
            int c0 = cb + n * 8, c1 = c0 + 1;
            if (c0 >= len) { c[n][0] = -1e30f; c[n][2] = -1e30f; }
            if (c1 >= len) { c[n][1] = -1e30f; c[n][3] = -1e30f; }
            mx0 = fmaxf(mx0, fmaxf(c[n][0], c[n][1]));
            mx1 = fmaxf(mx1, fmaxf(c[n][2], c[n][3]));
        }
        mx0 = fmaxf(mx0, __shfl_xor_sync(0xffffffffu, mx0, 1));
        mx0 = fmaxf(mx0, __shfl_xor_sync(0xffffffffu, mx0, 2));
        mx1 = fmaxf(mx1, __shfl_xor_sync(0xffffffffu, mx1, 1));
        mx1 = fmaxf(mx1, __shfl_xor_sync(0xffffffffu, mx1, 2));

        float mn0 = fmaxf(mr0, mx0), mn1 = fmaxf(mr1, mx1);
        float al0 = __expf(mr0 - mn0), al1 = __expf(mr1 - mn1);
        float rs0 = 0.f, rs1 = 0.f;
#pragma unroll
        for (int n = 0; n < 8; n++) {
            c[n][0] = __expf(c[n][0] - mn0);
            c[n][1] = __expf(c[n][1] - mn0);
            c[n][2] = __expf(c[n][2] - mn1);
            c[n][3] = __expf(c[n][3] - mn1);
            rs0 += c[n][0] + c[n][1];
            rs1 += c[n][2] + c[n][3];
        }
        rs0 += __shfl_xor_sync(0xffffffffu, rs0, 1);
        rs0 += __shfl_xor_sync(0xffffffffu, rs0, 2);
        rs1 += __shfl_xor_sync(0xffffffffu, rs1, 1);
        rs1 += __shfl_xor_sync(0xffffffffu, rs1, 2);
        lr0 = lr0 * al0 + rs0;
        lr1 = lr1 * al1 + rs1;
        mr0 = mn0; mr1 = mn1;
#pragma unroll
        for (int n = 0; n < 8; n++) {
            O[n][0] *= al0; O[n][1] *= al0;
            O[n][2] *= al1; O[n][3] *= al1;
        }

        // ---- write P (per-warp region, tf32-rounded) ----
#pragma unroll
        for (int n = 0; n < 8; n++) {
            int pc = n * 8 + 2 * tq;
            Pw[qid * KP + pc]           = tf32r(c[n][0]);
            Pw[qid * KP + pc + 1]       = tf32r(c[n][1]);
            Pw[(qid + 8) * KP + pc]     = tf32r(c[n][2]);
            Pw[(qid + 8) * KP + pc + 1] = tf32r(c[n][3]);
        }
        __syncwarp();

        // ---- O += P @ V ----
#pragma unroll
        for (int k8 = 0; k8 < 8; k8++) {
            int k = k8 * 8;
            unsigned ap0 = __float_as_uint(Pw[qid * KP + k + tq]);
            unsigned ap1 = __float_as_uint(Pw[(qid + 8) * KP + k + tq]);
            unsigned ap2 = __float_as_uint(Pw[qid * KP + k + tq + 4]);
            unsigned ap3 = __float_as_uint(Pw[(qid + 8) * KP + k + tq + 4]);
#pragma unroll
            for (int n = 0; n < 8; n++) {
                unsigned b0 = __float_as_uint(Vs[(k + tq) * VP + n * 8 + qid]);
                unsigned b1 = __float_as_uint(Vs[(k + tq + 4) * VP + n * 8 + qid]);
                MMA_TF32(O[n][0], O[n][1], O[n][2], O[n][3],
                         ap0, ap1, ap2, ap3, b0, b1);
            }
        }
        __syncwarp();
    }

    // ---- epilogue ----
    float inv0 = 1.f / lr0, inv1 = 1.f / lr1;
    size_t row0 = (size_t)(b * Sn + qt * 64 + m0 + qid);
#pragma unroll
    for (int n = 0; n < 8; n++) {
        int col = h * 64 + n * 8 + 2 * tq;
        *(float2*)(ctx + row0 * 512 + col) =
            make_float2(O[n][0] * inv0, O[n][1] * inv0);
        *(float2*)(ctx + (row0 + 8) * 512 + col) =
            make_float2(O[n][2] * inv1, O[n][3] * inv1);
    }
}

// ============================ add + layernorm ===============================
__device__ __forceinline__ float blk_sum_128(float v, float* red) {
#pragma unroll
    for (int o = 16; o; o >>= 1) v += __shfl_xor_sync(0xffffffffu, v, o);
    __syncthreads();
    if ((threadIdx.x & 31) == 0) red[threadIdx.x >> 5] = v;
    __syncthreads();
    return red[0] + red[1] + red[2] + red[3];
}

__global__ __launch_bounds__(128)
void add_ln_kernel(float* __restrict__ x, const float* __restrict__ hh,
                   const float* __restrict__ g, const float* __restrict__ be) {
    __shared__ float red[4];
    int row = blockIdx.x;
    int t = threadIdx.x;
    size_t off = (size_t)row * 512 + t * 4;
    float4 xv = *(float4*)(x + off);
    float4 hv = *(const float4*)(hh + off);
    float v0 = xv.x + hv.x, v1 = xv.y + hv.y, v2 = xv.z + hv.z, v3 = xv.w + hv.w;
    float mean = blk_sum_128(v0 + v1 + v2 + v3, red) * (1.f / 512.f);
    float d0 = v0 - mean, d1 = v1 - mean, d2 = v2 - mean, d3 = v3 - mean;
    float var = blk_sum_128(d0 * d0 + d1 * d1 + d2 * d2 + d3 * d3, red) * (1.f / 512.f);
    float rstd = rsqrtf(var + 1e-5f);
    float4 gv = *(const float4*)(g + t * 4);
    float4 bv = *(const float4*)(be + t * 4);
    float4 o;
    o.x = d0 * rstd * gv.x + bv.x;
    o.y = d1 * rstd * gv.y + bv.y;
    o.z = d2 * rstd * gv.z + bv.z;
    o.w = d3 * rstd * gv.w + bv.w;
    *(float4*)(x + off) = o;
}

// ============================ final head ====================================
__global__ __launch_bounds__(256)
void final_logits_kernel(const float* __restrict__ x, const float* __restrict__ addr,
                         const float* __restrict__ poi, const int* __restrict__ atype,
                         const float* __restrict__ Wa, const float* __restrict__ ba,
                         const float* __restrict__ Wout, const float* __restrict__ Wcomb,
                         const int* __restrict__ dlen, float* __restrict__ logits) {
    int warp = (blockIdx.x * blockDim.x + threadIdx.x) >> 5;
    int lane = threadIdx.x & 31;
    if (warp >= BSn) return;
    int b = warp >> 10;
    int s = warp & 1023;
    int t = atype[b];
    float aj = ba[lane]
             + addr[b]        * Wa[lane]
             + poi[t * 3 + 0] * Wa[32 + lane]
             + poi[t * 3 + 1] * Wa[64 + lane]
             + poi[t * 3 + 2] * Wa[96 + lane];
    const float* xr = x + (size_t)warp * 512;
    float acc = 0.f;
#pragma unroll 8
    for (int d = 0; d < 512; d++) acc += xr[d] * Wout[d * 32 + lane];
    float tv = tanhf(acc + aj) * Wcomb[lane];
#pragma unroll
    for (int o = 16; o; o >>= 1) tv += __shfl_xor_sync(0xffffffffu, tv, o);
    if (lane == 0) logits[warp] = (s < dlen[b]) ? tv : -1e9f;
}

__global__ __launch_bounds__(256)
void logsoftmax_kernel(const float* __restrict__ logits, const int* __restrict__ dlen,
                       float* __restrict__ out) {
    __shared__ float red[8];
    int b = blockIdx.x;
    int len = dlen[b];
    const float* lg = logits + (size_t)b * Sn;
    float mx = -1e30f;
    for (int s = threadIdx.x; s < len; s += 256) mx = fmaxf(mx, lg[s]);
#pragma unroll
    for (int o = 16; o; o >>= 1) mx = fmaxf(mx, __shfl_xor_sync(0xffffffffu, mx, o));
    if ((threadIdx.x & 31) == 0) red[threadIdx.x >> 5] = mx;
    __syncthreads();
    mx = red[0];
#pragma unroll
    for (int w = 1; w < 8; w++) mx = fmaxf(mx, red[w]);
    __syncthreads();
    float sum = 0.f;
    for (int s = threadIdx.x; s < len; s += 256) sum += expf(lg[s] - mx);
#pragma unroll
    for (int o = 16; o; o >>= 1) sum += __shfl_xor_sync(0xffffffffu, sum, o);
    if ((threadIdx.x & 31) == 0) red[threadIdx.x >> 5] = sum;
    __syncthreads();
    sum = red[0] + red[1] + red[2] + red[3] + red[4] + red[5] + red[6] + red[7];
    float lse = logf(sum) + mx;
    for (int s = threadIdx.x; s < Sn; s += 256)
        out[(size_t)b * Sn + s] = (s < len) ? (lg[s] - lse) : 0.f;
}

// ============================ launch ========================================
extern "C" void kernel_launch(void* const* d_in, const int* in_sizes, int n_in,
                              void* d_out, int out_size) {
    const float* addr  = (const float*)d_in[0];
    const float* loc   = (const float*)d_in[1];
    const float* tdist = (const float*)d_in[2];
    const float* Wtd   = (const float*)d_in[3];
    const float* btd   = (const float*)d_in[4];
    const float* Wemb  = (const float*)d_in[5];
    const float* bemb  = (const float*)d_in[6];
    const float* Wqkv  = (const float*)d_in[7];
    const float* bqkv  = (const float*)d_in[8];
    const float* Wo    = (const float*)d_in[9];
    const float* bo    = (const float*)d_in[10];
    const float* ln1g  = (const float*)d_in[11];
    const float* ln1b  = (const float*)d_in[12];
    const float* W1    = (const float*)d_in[13];
    const float* b1    = (const float*)d_in[14];
    const float* W2    = (const float*)d_in[15];
    const float* b2    = (const float*)d_in[16];
    const float* ln2g  = (const float*)d_in[17];
    const float* ln2b  = (const float*)d_in[18];
    const float* poi   = (const float*)d_in[19];
    const float* Wa    = (const float*)d_in[20];
    const float* ba    = (const float*)d_in[21];
    const float* Wout  = (const float*)d_in[22];
    const float* Wcomb = (const float*)d_in[23];
    const int*   atype = (const int*)d_in[24];
    const int*   dlen  = (const int*)d_in[25];
    float* out = (float*)d_out;

    float *x, *qkvb, *ctx, *t1, *t2, *lg;
    cudaGetSymbolAddress((void**)&x,    g_x);
    cudaGetSymbolAddress((void**)&qkvb, g_qkv);
    cudaGetSymbolAddress((void**)&ctx,  g_ctx);
    cudaGetSymbolAddress((void**)&t1,   g_t1);
    cudaGetSymbolAddress((void**)&t2,   g_t2);
    cudaGetSymbolAddress((void**)&lg,   g_logits);

    cudaFuncSetAttribute(flash_mma_kernel,
                         cudaFuncAttributeMaxDynamicSharedMemorySize, FLASH_SMEM);

    embed_kernel<<<BSn, 128>>>(loc, tdist, Wtd, btd, Wemb, bemb, x);

    for (int l = 0; l < Ln; l++) {
        tf32_gemm<0><<<dim3(12, 256), 256>>>(x, Wqkv + (size_t)l * Dn * 3 * Dn,
                                             bqkv + l * 3 * Dn, qkvb, BSn, 3 * Dn, Dn);
        flash_mma_kernel<<<dim3(16, Bn * Hn), 128, FLASH_SMEM>>>(qkvb, ctx, dlen);
        tf32_gemm<0><<<dim3(4, 256), 256>>>(ctx, Wo + (size_t)l * Dn * Dn,
                                            bo + l * Dn, t1, BSn, Dn, Dn);
        add_ln_kernel<<<BSn, 128>>>(x, t1, ln1g + l * Dn, ln1b + l * Dn);
        tf32_gemm<1><<<dim3(4, 256), 256>>>(x, W1 + (size_t)l * Dn * Dn,
                                            b1 + l * Dn, t2, BSn, Dn, Dn);
        tf32_gemm<0><<<dim3(4, 256), 256>>>(t2, W2 + (size_t)l * Dn * Dn,
                                            b2 + l * Dn, t1, BSn, Dn, Dn);
        add_ln_kernel<<<BSn, 128>>>(x, t1, ln2g + l * Dn, ln2b + l * Dn);
    }

    final_logits_kernel<<<(BSn * 32) / 256, 256>>>(x, addr, poi, atype, Wa, ba,
                                                   Wout, Wcomb, dlen, lg);
    logsoftmax_kernel<<<Bn, 256>>>(lg, dlen, out);
}

// round 6
// speedup vs baseline: 2.6020x; 1.0472x over previous
#include <cuda_runtime.h>
#include <math.h>
#include <stdint.h>

#define Bn   32
#define Sn   1024
#define Dn   512
#define Hn   8
#define Ln   4
#define DHn  64
#define BSn  (Bn*Sn)
#define FCn  32

// ------------------------- scratch (device globals; no allocs allowed) ------
__device__ float g_x[(size_t)BSn * Dn];
__device__ float g_qkv[(size_t)BSn * 3 * Dn];
__device__ float g_ctx[(size_t)BSn * Dn];
__device__ float g_t1[(size_t)BSn * Dn];
__device__ float g_t2[(size_t)BSn * Dn];
__device__ float g_logits[BSn];

__device__ __forceinline__ float tf32r(float x) {
    unsigned u;
    asm("cvt.rna.tf32.f32 %0, %1;" : "=r"(u) : "f"(x));
    return __uint_as_float(u);
}

__device__ __forceinline__ void cpa16(uint32_t dst, const void* src) {
    asm volatile("cp.async.cg.shared.global [%0], [%1], 16;" :: "r"(dst), "l"(src));
}
#define CP_COMMIT() asm volatile("cp.async.commit_group;")
#define CP_WAIT(N)  asm volatile("cp.async.wait_group %0;" :: "n"(N))

#define MMA_TF32(C0,C1,C2,C3,A0,A1,A2,A3,B0,B1)                              \
    asm volatile(                                                            \
        "mma.sync.aligned.m16n8k8.row.col.f32.tf32.tf32.f32 "                \
        "{%0,%1,%2,%3}, {%4,%5,%6,%7}, {%8,%9}, {%0,%1,%2,%3};"              \
        : "+f"(C0), "+f"(C1), "+f"(C2), "+f"(C3)                             \
        : "r"(A0), "r"(A1), "r"(A2), "r"(A3), "r"(B0), "r"(B1))

// ============================ embed =========================================
__global__ void embed_kernel(const float* __restrict__ loc,
                             const float* __restrict__ tdist,
                             const float* __restrict__ Wtd,
                             const float* __restrict__ btd,
                             const float* __restrict__ Wemb,
                             const float* __restrict__ bemb,
                             float* __restrict__ x) {
    int tok = blockIdx.x;
    const float* lp = loc + (size_t)tok * 16;
    const float* tp = tdist + (size_t)tok * 8;
    float in[19];
#pragma unroll
    for (int i = 0; i < 16; i++) in[i] = lp[i];
#pragma unroll
    for (int j = 0; j < 3; j++) {
        float s = btd[j];
#pragma unroll
        for (int i = 0; i < 8; i++) s += tp[i] * Wtd[i * 3 + j];
        in[16 + j] = s;
    }
    int d = threadIdx.x * 4;
    float4 acc = *(const float4*)(bemb + d);
#pragma unroll
    for (int i = 0; i < 19; i++) {
        float4 w = *(const float4*)(Wemb + i * 512 + d);
        float s = in[i];
        acc.x += s * w.x; acc.y += s * w.y; acc.z += s * w.z; acc.w += s * w.w;
    }
    *(float4*)(x + (size_t)tok * 512 + d) = acc;
}

// ============================ TF32 tensor-core GEMM (2-stage) ===============
#define SPITCH 136

template <int ACT>
__global__ __launch_bounds__(256)
void tf32_gemm(const float* __restrict__ A, const float* __restrict__ W,
               const float* __restrict__ bias, float* __restrict__ C,
               int M, int N, int K) {
    __shared__ float Sb[2][2][16][SPITCH];   // [stage][A/W][k][m or n]

    const int tid  = threadIdx.x;
    const int warp = tid >> 5;
    const int lane = tid & 31;
    const int wm = warp >> 2;
    const int wn = warp & 3;
    const int qid = lane >> 2;
    const int tq  = lane & 3;

    const int bm = blockIdx.y * 128;
    const int bn = blockIdx.x * 128;

    const int arow = tid >> 1;
    const int acol = (tid & 1) << 3;
    const int wrow = tid >> 4;
    const int wcol = (tid & 15) << 3;

    const float* Ap = A + (size_t)(bm + arow) * K + acol;
    const float* Wp = W + (size_t)wrow * N + bn + wcol;

    float4 ra0 = *(const float4*)(Ap);
    float4 ra1 = *(const float4*)(Ap + 4);
    float4 rw0 = *(const float4*)(Wp);
    float4 rw1 = *(const float4*)(Wp + 4);

    float acc[4][4][4];
#pragma unroll
    for (int i = 0; i < 4; i++)
#pragma unroll
        for (int j = 0; j < 4; j++)
#pragma unroll
            for (int c = 0; c < 4; c++) acc[i][j][c] = 0.f;

    // stage 0 store
    {
        float* As = &Sb[0][0][0][0];
        float* Ws = &Sb[0][1][0][0];
        As[(acol + 0) * SPITCH + arow] = tf32r(ra0.x);
        As[(acol + 1) * SPITCH + arow] = tf32r(ra0.y);
        As[(acol + 2) * SPITCH + arow] = tf32r(ra0.z);
        As[(acol + 3) * SPITCH + arow] = tf32r(ra0.w);
        As[(acol + 4) * SPITCH + arow] = tf32r(ra1.x);
        As[(acol + 5) * SPITCH + arow] = tf32r(ra1.y);
        As[(acol + 6) * SPITCH + arow] = tf32r(ra1.z);
        As[(acol + 7) * SPITCH + arow] = tf32r(ra1.w);
        Ws[wrow * SPITCH + wcol + 0] = tf32r(rw0.x);
        Ws[wrow * SPITCH + wcol + 1] = tf32r(rw0.y);
        Ws[wrow * SPITCH + wcol + 2] = tf32r(rw0.z);
        Ws[wrow * SPITCH + wcol + 3] = tf32r(rw0.w);
        Ws[wrow * SPITCH + wcol + 4] = tf32r(rw1.x);
        Ws[wrow * SPITCH + wcol + 5] = tf32r(rw1.y);
        Ws[wrow * SPITCH + wcol + 6] = tf32r(rw1.z);
        Ws[wrow * SPITCH + wcol + 7] = tf32r(rw1.w);
    }

    const int K16 = K >> 4;
    for (int kc = 0; kc < K16; kc++) {
        const int s = kc & 1;
        __syncthreads();

        const bool more = (kc + 1 < K16);
        if (more) {
            int k0 = (kc + 1) << 4;
            ra0 = *(const float4*)(Ap + k0);
            ra1 = *(const float4*)(Ap + k0 + 4);
            rw0 = *(const float4*)(Wp + (size_t)k0 * N);
            rw1 = *(const float4*)(Wp + (size_t)k0 * N + 4);
        }

        const float (*As)[SPITCH] = Sb[s][0];
        const float (*Ws)[SPITCH] = Sb[s][1];
#pragma unroll
        for (int kk = 0; kk < 16; kk += 8) {
            unsigned a[4][4], b[4][2];
#pragma unroll
            for (int am = 0; am < 4; am++) {
                int m0 = wm * 64 + am * 16;
                a[am][0] = __float_as_uint(As[kk + tq][m0 + qid]);
                a[am][1] = __float_as_uint(As[kk + tq][m0 + qid + 8]);
                a[am][2] = __float_as_uint(As[kk + tq + 4][m0 + qid]);
                a[am][3] = __float_as_uint(As[kk + tq + 4][m0 + qid + 8]);
            }
#pragma unroll
            for (int an = 0; an < 4; an++) {
                int n0 = wn * 32 + an * 8;
                b[an][0] = __float_as_uint(Ws[kk + tq][n0 + qid]);
                b[an][1] = __float_as_uint(Ws[kk + tq + 4][n0 + qid]);
            }
#pragma unroll
            for (int am = 0; am < 4; am++)
#pragma unroll
                for (int an = 0; an < 4; an++)
                    MMA_TF32(acc[am][an][0], acc[am][an][1],
                             acc[am][an][2], acc[am][an][3],
                             a[am][0], a[am][1], a[am][2], a[am][3],
                             b[an][0], b[an][1]);
        }

        if (more) {
            float* Asn = &Sb[s ^ 1][0][0][0];
            float* Wsn = &Sb[s ^ 1][1][0][0];
            Asn[(acol + 0) * SPITCH + arow] = tf32r(ra0.x);
            Asn[(acol + 1) * SPITCH + arow] = tf32r(ra0.y);
            Asn[(acol + 2) * SPITCH + arow] = tf32r(ra0.z);
            Asn[(acol + 3) * SPITCH + arow] = tf32r(ra0.w);
            Asn[(acol + 4) * SPITCH + arow] = tf32r(ra1.x);
            Asn[(acol + 5) * SPITCH + arow] = tf32r(ra1.y);
            Asn[(acol + 6) * SPITCH + arow] = tf32r(ra1.z);
            Asn[(acol + 7) * SPITCH + arow] = tf32r(ra1.w);
            Wsn[wrow * SPITCH + wcol + 0] = tf32r(rw0.x);
            Wsn[wrow * SPITCH + wcol + 1] = tf32r(rw0.y);
            Wsn[wrow * SPITCH + wcol + 2] = tf32r(rw0.z);
            Wsn[wrow * SPITCH + wcol + 3] = tf32r(rw0.w);
            Wsn[wrow * SPITCH + wcol + 4] = tf32r(rw1.x);
            Wsn[wrow * SPITCH + wcol + 5] = tf32r(rw1.y);
            Wsn[wrow * SPITCH + wcol + 6] = tf32r(rw1.z);
            Wsn[wrow * SPITCH + wcol + 7] = tf32r(rw1.w);
        }
    }

#pragma unroll
    for (int am = 0; am < 4; am++) {
        int r0 = bm + wm * 64 + am * 16 + qid;
#pragma unroll
        for (int an = 0; an < 4; an++) {
            int col = bn + wn * 32 + an * 8 + 2 * tq;
            float b0 = bias[col], b1 = bias[col + 1];
            float v0 = acc[am][an][0] + b0;
            float v1 = acc[am][an][1] + b1;
            float v2 = acc[am][an][2] + b0;
            float v3 = acc[am][an][3] + b1;
            if (ACT) {
                v0 = fmaxf(v0, 0.f); v1 = fmaxf(v1, 0.f);
                v2 = fmaxf(v2, 0.f); v3 = fmaxf(v3, 0.f);
            }
            *(float2*)(C + (size_t)r0 * N + col)       = make_float2(v0, v1);
            *(float2*)(C + (size_t)(r0 + 8) * N + col) = make_float2(v2, v3);
        }
    }
}

// ============================ flash attention (TF32 mma, 2-stage) ===========
// block 256 thr (8 warps), 128 q-rows per block, warp tile m=16.
// K/V double-buffered via cp.async. Q staged then reused as per-warp P tiles.
#define KP 68
#define VP 72
#define STG (64 * KP + 64 * VP)
#define FLASH_SMEM ((2 * STG + 128 * KP) * 4)

__global__ __launch_bounds__(256)
void flash_mma_kernel(const float* __restrict__ qkv, float* __restrict__ ctx,
                      const int* __restrict__ dlen) {
    extern __shared__ float sm[];

    const int qt = blockIdx.x;
    const int bh = blockIdx.y;
    const int b  = bh >> 3;
    const int h  = bh & 7;
    const int len = dlen[b];
    const int nk = (len + 63) >> 6;

    const int tid = threadIdx.x;
    const int warp = tid >> 5;
    const int lane = tid & 31;
    const int qid = lane >> 2;
    const int tq  = lane & 3;
    const int m0  = warp * 16;

    const float* qbase = qkv + (size_t)b * Sn * 1536 + h * 64;
    const float* kbase = qbase + 512;
    const float* vbase = qbase + 1024;

    float* Qs = sm + 2 * STG;       // [128][KP], later per-warp P
    uint32_t smbase = (uint32_t)__cvta_generic_to_shared(sm);

    // ---- prologue: issue K/V tile 0 via cp.async ----
    {
        uint32_t kd = smbase;
        uint32_t vd = smbase + 64 * KP * 4;
#pragma unroll
        for (int u = 0; u < 4; u++) {
            int f = tid + u * 256;
            int r = f >> 4, c = (f & 15) << 2;
            size_t grow = (size_t)r * 1536 + c;
            cpa16(kd + (r * KP + c) * 4, kbase + grow);
            cpa16(vd + (r * VP + c) * 4, vbase + grow);
        }
        CP_COMMIT();
    }

    // ---- load Q tile (scaled, tf32-rounded) ----
    {
        const float scale = 0.125f;
#pragma unroll
        for (int u = 0; u < 8; u++) {
            int f = tid + u * 256;
            int r = f >> 4, c = (f & 15) << 2;
            float4 v = *(const float4*)(qbase + (size_t)(qt * 128 + r) * 1536 + c);
            v.x = tf32r(v.x * scale); v.y = tf32r(v.y * scale);
            v.z = tf32r(v.z * scale); v.w = tf32r(v.w * scale);
            *(float4*)(Qs + r * KP + c) = v;
        }
    }
    __syncthreads();

    // ---- Q register fragments ----
    unsigned aq[8][4];
#pragma unroll
    for (int k8 = 0; k8 < 8; k8++) {
        int k = k8 * 8;
        aq[k8][0] = __float_as_uint(Qs[(m0 + qid) * KP + k + tq]);
        aq[k8][1] = __float_as_uint(Qs[(m0 + qid + 8) * KP + k + tq]);
        aq[k8][2] = __float_as_uint(Qs[(m0 + qid) * KP + k + tq + 4]);
        aq[k8][3] = __float_as_uint(Qs[(m0 + qid + 8) * KP + k + tq + 4]);
    }

    float* Pw = Qs + m0 * KP;       // per-warp P tile [16][KP] (own rows only)

    float mr0 = -1e30f, mr1 = -1e30f, lr0 = 0.f, lr1 = 0.f;
    float O[8][4];
#pragma unroll
    for (int n = 0; n < 8; n++)
#pragma unroll
        for (int c = 0; c < 4; c++) O[n][c] = 0.f;

    for (int kt = 0; kt < nk; kt++) {
        __syncthreads();            // everyone done with stage (kt+1)&1 data
        if (kt + 1 < nk) {
            uint32_t sb = smbase + ((kt + 1) & 1) * STG * 4;
            uint32_t kd = sb;
            uint32_t vd = sb + 64 * KP * 4;
#pragma unroll
            for (int u = 0; u < 4; u++) {
                int f = tid + u * 256;
                int r = f >> 4, c = (f & 15) << 2;
                size_t grow = (size_t)((kt + 1) * 64 + r) * 1536 + c;
                cpa16(kd + (r * KP + c) * 4, kbase + grow);
                cpa16(vd + (r * VP + c) * 4, vbase + grow);
            }
            CP_COMMIT();
            CP_WAIT(1);
        } else {
            CP_WAIT(0);
        }
        __syncthreads();            // tile kt visible to all

        const float* Ks = sm + (kt & 1) * STG;
        const float* Vs = Ks + 64 * KP;

        // ---- S = Q @ K^T ----
        float c[8][4];
#pragma unroll
        for (int n = 0; n < 8; n++)
#pragma unroll
            for (int j = 0; j < 4; j++) c[n][j] = 0.f;

#pragma unroll
        for (int k8 = 0; k8 < 8; k8++) {
            int k = k8 * 8;
#pragma unroll
            for (int n = 0; n < 8; n++) {
                unsigned b0 = __float_as_uint(Ks[(n * 8 + qid) * KP + k + tq]);
                unsigned b1 = __float_as_uint(Ks[(n * 8 + qid) * KP + k + tq + 4]);
                MMA_TF32(c[n][0], c[n][1], c[n][2], c[n][3],
                         aq[k8][0], aq[k8][1], aq[k8][2], aq[k8][3], b0, b1);
            }
        }

        // ---- mask + online softmax ----
        const int cb = kt * 64 + 2 * tq;
        float mx0 = -1e30f, mx1 = -1e30f;
#pragma unroll
        for (int n = 0; n < 8; n++) {
            int c0 = cb + n * 8, c1 = c0 + 1;
            if (c0 >= len) { c[n][0] = -1e30f; c[n][2] = -1e30f; }
            if (c1 >= len) { c[n][1] = -1e30f; c[n][3] = -1e30f; }
            mx0 = fmaxf(mx0, fmaxf(c[n][0], c[n][1]));
            mx1 = fmaxf(mx1, fmaxf(c[n][2], c[n][3]));
        }
        mx0 = fmaxf(mx0, __shfl_xor_sync(0xffffffffu, mx0, 1));
        mx0 = fmaxf(mx0, __shfl_xor_sync(0xffffffffu, mx0, 2));
        mx1 = fmaxf(mx1, __shfl_xor_sync(0xffffffffu, mx1, 1));
        mx1 = fmaxf(mx1, __shfl_xor_sync(0xffffffffu, mx1, 2));

        float mn0 = fmaxf(mr0, mx0), mn1 = fmaxf(mr1, mx1);
        float al0 = __expf(mr0 - mn0), al1 = __expf(mr1 - mn1);
        float rs0 = 0.f, rs1 = 0.f;
#pragma unroll
        for (int n = 0; n < 8; n++) {
            c[n][0] = __expf(c[n][0] - mn0);
            c[n][1] = __expf(c[n][1] - mn0);
            c[n][2] = __expf(c[n][2] - mn1);
            c[n][3] = __expf(c[n][3] - mn1);
            rs0 += c[n][0] + c[n][1];
            rs1 += c[n][2] + c[n][3];
        }
        rs0 += __shfl_xor_sync(0xffffffffu, rs0, 1);
        rs0 += __shfl_xor_sync(0xffffffffu, rs0, 2);
        rs1 += __shfl_xor_sync(0xffffffffu, rs1, 1);
        rs1 += __shfl_xor_sync(0xffffffffu, rs1, 2);
        lr0 = lr0 * al0 + rs0;
        lr1 = lr1 * al1 + rs1;
        mr0 = mn0; mr1 = mn1;
#pragma unroll
        for (int n = 0; n < 8; n++) {
            O[n][0] *= al0; O[n][1] *= al0;
            O[n][2] *= al1; O[n][3] *= al1;
        }

        // ---- write P (per-warp region) ----
#pragma unroll
        for (int n = 0; n < 8; n++) {
            int pc = n * 8 + 2 * tq;
            Pw[qid * KP + pc]           = tf32r(c[n][0]);
            Pw[qid * KP + pc + 1]       = tf32r(c[n][1]);
            Pw[(qid + 8) * KP + pc]     = tf32r(c[n][2]);
            Pw[(qid + 8) * KP + pc + 1] = tf32r(c[n][3]);
        }
        __syncwarp();

        // ---- O += P @ V ----
#pragma unroll
        for (int k8 = 0; k8 < 8; k8++) {
            int k = k8 * 8;
            unsigned ap0 = __float_as_uint(Pw[qid * KP + k + tq]);
            unsigned ap1 = __float_as_uint(Pw[(qid + 8) * KP + k + tq]);
            unsigned ap2 = __float_as_uint(Pw[qid * KP + k + tq + 4]);
            unsigned ap3 = __float_as_uint(Pw[(qid + 8) * KP + k + tq + 4]);
#pragma unroll
            for (int n = 0; n < 8; n++) {
                unsigned b0 = __float_as_uint(Vs[(k + tq) * VP + n * 8 + qid]);
                unsigned b1 = __float_as_uint(Vs[(k + tq + 4) * VP + n * 8 + qid]);
                MMA_TF32(O[n][0], O[n][1], O[n][2], O[n][3],
                         ap0, ap1, ap2, ap3, b0, b1);
            }
        }
        __syncwarp();
    }

    // ---- epilogue ----
    float inv0 = 1.f / lr0, inv1 = 1.f / lr1;
    size_t row0 = (size_t)(b * Sn + qt * 128 + m0 + qid);
#pragma unroll
    for (int n = 0; n < 8; n++) {
        int col = h * 64 + n * 8 + 2 * tq;
        *(float2*)(ctx + row0 * 512 + col) =
            make_float2(O[n][0] * inv0, O[n][1] * inv0);
        *(float2*)(ctx + (row0 + 8) * 512 + col) =
            make_float2(O[n][2] * inv1, O[n][3] * inv1);
    }
}

// ============================ add + layernorm ===============================
__device__ __forceinline__ float blk_sum_128(float v, float* red) {
#pragma unroll
    for (int o = 16; o; o >>= 1) v += __shfl_xor_sync(0xffffffffu, v, o);
    __syncthreads();
    if ((threadIdx.x & 31) == 0) red[threadIdx.x >> 5] = v;
    __syncthreads();
    return red[0] + red[1] + red[2] + red[3];
}

__global__ __launch_bounds__(128)
void add_ln_kernel(float* __restrict__ x, const float* __restrict__ hh,
                   const float* __restrict__ g, const float* __restrict__ be) {
    __shared__ float red[4];
    int row = blockIdx.x;
    int t = threadIdx.x;
    size_t off = (size_t)row * 512 + t * 4;
    float4 xv = *(float4*)(x + off);
    float4 hv = *(const float4*)(hh + off);
    float v0 = xv.x + hv.x, v1 = xv.y + hv.y, v2 = xv.z + hv.z, v3 = xv.w + hv.w;
    float mean = blk_sum_128(v0 + v1 + v2 + v3, red) * (1.f / 512.f);
    float d0 = v0 - mean, d1 = v1 - mean, d2 = v2 - mean, d3 = v3 - mean;
    float var = blk_sum_128(d0 * d0 + d1 * d1 + d2 * d2 + d3 * d3, red) * (1.f / 512.f);
    float rstd = rsqrtf(var + 1e-5f);
    float4 gv = *(const float4*)(g + t * 4);
    float4 bv = *(const float4*)(be + t * 4);
    float4 o;
    o.x = d0 * rstd * gv.x + bv.x;
    o.y = d1 * rstd * gv.y + bv.y;
    o.z = d2 * rstd * gv.z + bv.z;
    o.w = d3 * rstd * gv.w + bv.w;
    *(float4*)(x + off) = o;
}

// ============================ final head (smem-cached Wout) =================
#define HEAD_SMEM (512 * 32 * 4)

__global__ __launch_bounds__(256)
void final_logits_kernel(const float* __restrict__ x, const float* __restrict__ addr,
                         const float* __restrict__ poi, const int* __restrict__ atype,
                         const float* __restrict__ Wa, const float* __restrict__ ba,
                         const float* __restrict__ Wout, const float* __restrict__ Wcomb,
                         const int* __restrict__ dlen, float* __restrict__ logits) {
    extern __shared__ float ws[];   // Wout [512][32]
    for (int i = threadIdx.x; i < 512 * 32; i += 256) ws[i] = Wout[i];
    __syncthreads();

    const int warp = threadIdx.x >> 5;
    const int lane = threadIdx.x & 31;
    const float wc = Wcomb[lane];

    for (int tok = blockIdx.x * 8 + warp; tok < BSn; tok += gridDim.x * 8) {
        int b = tok >> 10;
        int s = tok & 1023;
        int t = atype[b];
        float aj = ba[lane]
                 + addr[b]        * Wa[lane]
                 + poi[t * 3 + 0] * Wa[32 + lane]
                 + poi[t * 3 + 1] * Wa[64 + lane]
                 + poi[t * 3 + 2] * Wa[96 + lane];
        const float* xr = x + (size_t)tok * 512;
        float acc = 0.f;
        for (int d0 = 0; d0 < 512; d0 += 32) {
            float xv = xr[d0 + lane];
#pragma unroll
            for (int j = 0; j < 32; j++)
                acc += __shfl_sync(0xffffffffu, xv, j) * ws[(d0 + j) * 32 + lane];
        }
        float tv = tanhf(acc + aj) * wc;
#pragma unroll
        for (int o = 16; o; o >>= 1) tv += __shfl_xor_sync(0xffffffffu, tv, o);
        if (lane == 0) logits[tok] = (s < dlen[b]) ? tv : -1e9f;
    }
}

__global__ __launch_bounds__(256)
void logsoftmax_kernel(const float* __restrict__ logits, const int* __restrict__ dlen,
                       float* __restrict__ out) {
    __shared__ float red[8];
    int b = blockIdx.x;
    int len = dlen[b];
    const float* lg = logits + (size_t)b * Sn;
    float mx = -1e30f;
    for (int s = threadIdx.x; s < len; s += 256) mx = fmaxf(mx, lg[s]);
#pragma unroll
    for (int o = 16; o; o >>= 1) mx = fmaxf(mx, __shfl_xor_sync(0xffffffffu, mx, o));
    if ((threadIdx.x & 31) == 0) red[threadIdx.x >> 5] = mx;
    __syncthreads();
    mx = red[0];
#pragma unroll
    for (int w = 1; w < 8; w++) mx = fmaxf(mx, red[w]);
    __syncthreads();
    float sum = 0.f;
    for (int s = threadIdx.x; s < len; s += 256) sum += expf(lg[s] - mx);
#pragma unroll
    for (int o = 16; o; o >>= 1) sum += __shfl_xor_sync(0xffffffffu, sum, o);
    if ((threadIdx.x & 31) == 0) red[threadIdx.x >> 5] = sum;
    __syncthreads();
    sum = red[0] + red[1] + red[2] + red[3] + red[4] + red[5] + red[6] + red[7];
    float lse = logf(sum) + mx;
    for (int s = threadIdx.x; s < Sn; s += 256)
        out[(size_t)b * Sn + s] = (s < len) ? (lg[s] - lse) : 0.f;
}

// ============================ launch ========================================
extern "C" void kernel_launch(void* const* d_in, const int* in_sizes, int n_in,
                              void* d_out, int out_size) {
    const float* addr  = (const float*)d_in[0];
    const float* loc   = (const float*)d_in[1];
    const float* tdist = (const float*)d_in[2];
    const float* Wtd   = (const float*)d_in[3];
    const float* btd   = (const float*)d_in[4];
    const float* Wemb  = (const float*)d_in[5];
    const float* bemb  = (const float*)d_in[6];
    const float* Wqkv  = (const float*)d_in[7];
    const float* bqkv  = (const float*)d_in[8];
    const float* Wo    = (const float*)d_in[9];
    const float* bo    = (const float*)d_in[10];
    const float* ln1g  = (const float*)d_in[11];
    const float* ln1b  = (const float*)d_in[12];
    const float* W1    = (const float*)d_in[13];
    const float* b1    = (const float*)d_in[14];
    const float* W2    = (const float*)d_in[15];
    const float* b2    = (const float*)d_in[16];
    const float* ln2g  = (const float*)d_in[17];
    const float* ln2b  = (const float*)d_in[18];
    const float* poi   = (const float*)d_in[19];
    const float* Wa    = (const float*)d_in[20];
    const float* ba    = (const float*)d_in[21];
    const float* Wout  = (const float*)d_in[22];
    const float* Wcomb = (const float*)d_in[23];
    const int*   atype = (const int*)d_in[24];
    const int*   dlen  = (const int*)d_in[25];
    float* out = (float*)d_out;

    float *x, *qkvb, *ctx, *t1, *t2, *lg;
    cudaGetSymbolAddress((void**)&x,    g_x);
    cudaGetSymbolAddress((void**)&qkvb, g_qkv);
    cudaGetSymbolAddress((void**)&ctx,  g_ctx);
    cudaGetSymbolAddress((void**)&t1,   g_t1);
    cudaGetSymbolAddress((void**)&t2,   g_t2);
    cudaGetSymbolAddress((void**)&lg,   g_logits);

    cudaFuncSetAttribute(flash_mma_kernel,
                         cudaFuncAttributeMaxDynamicSharedMemorySize, FLASH_SMEM);
    cudaFuncSetAttribute(final_logits_kernel,
                         cudaFuncAttributeMaxDynamicSharedMemorySize, HEAD_SMEM);

    embed_kernel<<<BSn, 128>>>(loc, tdist, Wtd, btd, Wemb, bemb, x);

    for (int l = 0; l < Ln; l++) {
        tf32_gemm<0><<<dim3(12, 256), 256>>>(x, Wqkv + (size_t)l * Dn * 3 * Dn,
                                             bqkv + l * 3 * Dn, qkvb, BSn, 3 * Dn, Dn);
        flash_mma_kernel<<<dim3(8, Bn * Hn), 256, FLASH_SMEM>>>(qkvb, ctx, dlen);
        tf32_gemm<0><<<dim3(4, 256), 256>>>(ctx, Wo + (size_t)l * Dn * Dn,
                                            bo + l * Dn, t1, BSn, Dn, Dn);
        add_ln_kernel<<<BSn, 128>>>(x, t1, ln1g + l * Dn, ln1b + l * Dn);
        tf32_gemm<1><<<dim3(4, 256), 256>>>(x, W1 + (size_t)l * Dn * Dn,
                                            b1 + l * Dn, t2, BSn, Dn, Dn);
        tf32_gemm<0><<<dim3(4, 256), 256>>>(t2, W2 + (size_t)l * Dn * Dn,
                                            b2 + l * Dn, t1, BSn, Dn, Dn);
        add_ln_kernel<<<BSn, 128>>>(x, t1, ln2g + l * Dn, ln2b + l * Dn);
    }

    final_logits_kernel<<<512, 256, HEAD_SMEM>>>(x, addr, poi, atype, Wa, ba,
                                                 Wout, Wcomb, dlen, lg);
    logsoftmax_kernel<<<Bn, 256>>>(lg, dlen, out);
}

// round 8
// speedup vs baseline: 4.5993x; 1.7676x over previous
#include <cuda_runtime.h>
#include <math.h>
#include <stdint.h>

#define Bn   32
#define Sn   1024
#define Dn   512
#define Hn   8
#define Ln   4
#define BSn  (Bn*Sn)

// ------------------------- scratch (device globals) -------------------------
__device__ float    g_x[(size_t)BSn * Dn];
__device__ uint32_t g_xpk[(size_t)BSn * 256];
__device__ uint32_t g_qpk[(size_t)256 * 1024 * 32];
__device__ uint32_t g_kpk[(size_t)256 * 1024 * 32];
__device__ float    g_vtmp[(size_t)256 * 1024 * 64];
__device__ uint32_t g_vpk[(size_t)256 * 512 * 64];
__device__ uint32_t g_ctxpk[(size_t)BSn * 256];
__device__ float    g_t1[(size_t)BSn * Dn];
__device__ uint32_t g_t2pk[(size_t)BSn * 256];
__device__ uint32_t g_wqkv[(size_t)Ln * 256 * 1536];
__device__ uint32_t g_wo[(size_t)Ln * 256 * 512];
__device__ uint32_t g_w1[(size_t)Ln * 256 * 512];
__device__ uint32_t g_w2[(size_t)Ln * 256 * 512];
__device__ float    g_logits[BSn];

// pack two fp32 into bf16x2: low half = first arg (even k), high = second
__device__ __forceinline__ uint32_t pk2(float lo, float hi) {
    uint32_t r;
    asm("cvt.rn.bf16x2.f32 %0, %1, %2;" : "=r"(r) : "f"(hi), "f"(lo));
    return r;
}

__device__ __forceinline__ void cpa16(uint32_t dst, const void* src) {
    asm volatile("cp.async.cg.shared.global [%0], [%1], 16;" :: "r"(dst), "l"(src));
}
#define CP_COMMIT() asm volatile("cp.async.commit_group;")
#define CP_WAIT(N)  asm volatile("cp.async.wait_group %0;" :: "n"(N))

#define MMA_BF16(C0,C1,C2,C3,A0,A1,A2,A3,B0,B1)                              \
    asm volatile(                                                            \
        "mma.sync.aligned.m16n8k16.row.col.f32.bf16.bf16.f32 "               \
        "{%0,%1,%2,%3}, {%4,%5,%6,%7}, {%8,%9}, {%0,%1,%2,%3};"              \
        : "+f"(C0), "+f"(C1), "+f"(C2), "+f"(C3)                             \
        : "r"(A0), "r"(A1), "r"(A2), "r"(A3), "r"(B0), "r"(B1))

// ============================ weight pack ===================================
__global__ void pack_w_kernel(const float* __restrict__ src,
                              uint32_t* __restrict__ dst, int KpT, int N) {
    int idx = blockIdx.x * 256 + threadIdx.x;
    if (idx >= KpT * N) return;
    int kp = idx / N;
    int n  = idx - kp * N;
    dst[idx] = pk2(src[(size_t)(2 * kp) * N + n], src[(size_t)(2 * kp + 1) * N + n]);
}

// ============================ embed =========================================
__global__ void embed_kernel(const float* __restrict__ loc,
                             const float* __restrict__ tdist,
                             const float* __restrict__ Wtd,
                             const float* __restrict__ btd,
                             const float* __restrict__ Wemb,
                             const float* __restrict__ bemb,
                             float* __restrict__ x,
                             uint32_t* __restrict__ xpk) {
    int tok = blockIdx.x;
    const float* lp = loc + (size_t)tok * 16;
    const float* tp = tdist + (size_t)tok * 8;
    float in[19];
#pragma unroll
    for (int i = 0; i < 16; i++) in[i] = lp[i];
#pragma unroll
    for (int j = 0; j < 3; j++) {
        float s = btd[j];
#pragma unroll
        for (int i = 0; i < 8; i++) s += tp[i] * Wtd[i * 3 + j];
        in[16 + j] = s;
    }
    int d = threadIdx.x * 4;
    float4 acc = *(const float4*)(bemb + d);
#pragma unroll
    for (int i = 0; i < 19; i++) {
        float4 w = *(const float4*)(Wemb + i * 512 + d);
        float s = in[i];
        acc.x += s * w.x; acc.y += s * w.y; acc.z += s * w.z; acc.w += s * w.w;
    }
    *(float4*)(x + (size_t)tok * 512 + d) = acc;
    uint2 p;
    p.x = pk2(acc.x, acc.y);
    p.y = pk2(acc.z, acc.w);
    *(uint2*)(xpk + (size_t)tok * 256 + threadIdx.x * 2) = p;
}

// ============================ bf16 tensor-core GEMM =========================
// A packed [M][Kp] bf16x2 (k-pairs), W packed [Kp][N].
// Block 128x128, chunk K=16 (8 k-pairs), 8 warps 2x4, warp tile 64x32.
// MODE 0: fp32 out. MODE 1: relu + packed bf16 out. MODE 2: QKV special.
template <int MODE>
__global__ __launch_bounds__(256)
void bf16_gemm(const uint32_t* __restrict__ Apk, const uint32_t* __restrict__ Wpk,
               const float* __restrict__ bias,
               float* __restrict__ Cf, uint32_t* __restrict__ Cpk,
               uint32_t* __restrict__ Qpk, uint32_t* __restrict__ Kpk,
               float* __restrict__ Vtmp,
               int M, int N, int Kp) {
    __shared__ uint32_t As[2][128 * 12];   // [m][kpair] pitch 12
    __shared__ uint32_t Ws[2][8 * 136];    // [kpair][n] pitch 136

    const int tid  = threadIdx.x;
    const int warp = tid >> 5;
    const int lane = tid & 31;
    const int wm = warp >> 2;
    const int wn = warp & 3;
    const int qid = lane >> 2;
    const int tq  = lane & 3;

    const int bm = blockIdx.y * 128;
    const int bn = blockIdx.x * 128;

    const int arow = tid >> 1;
    const int akp  = (tid & 1) << 2;       // 0 or 4
    const int wkp  = tid >> 5;             // 0..7
    const int wn4  = (tid & 31) << 2;      // 0..124

    const uint32_t* Ag = Apk + (size_t)(bm + arow) * Kp + akp;
    const uint32_t* Wg = Wpk + (size_t)wkp * N + bn + wn4;

    uint32_t aAd[2], aWd[2];
    {
        uint32_t a0 = (uint32_t)__cvta_generic_to_shared(&As[0][0]);
        uint32_t a1 = (uint32_t)__cvta_generic_to_shared(&As[1][0]);
        uint32_t w0 = (uint32_t)__cvta_generic_to_shared(&Ws[0][0]);
        uint32_t w1 = (uint32_t)__cvta_generic_to_shared(&Ws[1][0]);
        aAd[0] = a0 + (arow * 12 + akp) * 4;
        aAd[1] = a1 + (arow * 12 + akp) * 4;
        aWd[0] = w0 + (wkp * 136 + wn4) * 4;
        aWd[1] = w1 + (wkp * 136 + wn4) * 4;
    }

    // prologue: chunk 0
    cpa16(aAd[0], Ag);
    cpa16(aWd[0], Wg);
    CP_COMMIT();

    float acc[4][4][4];
#pragma unroll
    for (int i = 0; i < 4; i++)
#pragma unroll
        for (int j = 0; j < 4; j++)
#pragma unroll
            for (int c = 0; c < 4; c++) acc[i][j][c] = 0.f;

    const int nck = Kp >> 3;
    for (int kc = 0; kc < nck; kc++) {
        const int s = kc & 1;
        if (kc + 1 < nck) {
            cpa16(aAd[s ^ 1], Ag + (kc + 1) * 8);
            cpa16(aWd[s ^ 1], Wg + (size_t)(kc + 1) * 8 * N);
            CP_COMMIT();
            CP_WAIT(1);
        } else {
            CP_WAIT(0);
        }
        __syncthreads();

        const uint32_t* as_ = As[s];
        const uint32_t* ws_ = Ws[s];
        unsigned a[4][4], b[4][2];
#pragma unroll
        for (int am = 0; am < 4; am++) {
            int m = wm * 64 + am * 16;
            a[am][0] = as_[(m + qid) * 12 + tq];
            a[am][1] = as_[(m + qid + 8) * 12 + tq];
            a[am][2] = as_[(m + qid) * 12 + tq + 4];
            a[am][3] = as_[(m + qid + 8) * 12 + tq + 4];
        }
#pragma unroll
        for (int an = 0; an < 4; an++) {
            int n0 = wn * 32 + an * 8;
            b[an][0] = ws_[tq * 136 + n0 + qid];
            b[an][1] = ws_[(tq + 4) * 136 + n0 + qid];
        }
#pragma unroll
        for (int am = 0; am < 4; am++)
#pragma unroll
            for (int an = 0; an < 4; an++)
                MMA_BF16(acc[am][an][0], acc[am][an][1],
                         acc[am][an][2], acc[am][an][3],
                         a[am][0], a[am][1], a[am][2], a[am][3],
                         b[an][0], b[an][1]);
        __syncthreads();
    }

    // epilogue
#pragma unroll
    for (int am = 0; am < 4; am++) {
        int r0 = bm + wm * 64 + am * 16 + qid;
#pragma unroll
        for (int an = 0; an < 4; an++) {
            int col = bn + wn * 32 + an * 8 + 2 * tq;
            float b0 = bias[col], b1 = bias[col + 1];
            float v0 = acc[am][an][0] + b0;
            float v1 = acc[am][an][1] + b1;
            float v2 = acc[am][an][2] + b0;
            float v3 = acc[am][an][3] + b1;
            if (MODE == 0) {
                *(float2*)(Cf + (size_t)r0 * N + col)       = make_float2(v0, v1);
                *(float2*)(Cf + (size_t)(r0 + 8) * N + col) = make_float2(v2, v3);
            } else if (MODE == 1) {
                v0 = fmaxf(v0, 0.f); v1 = fmaxf(v1, 0.f);
                v2 = fmaxf(v2, 0.f); v3 = fmaxf(v3, 0.f);
                Cpk[(size_t)r0 * (N >> 1) + (col >> 1)]       = pk2(v0, v1);
                Cpk[(size_t)(r0 + 8) * (N >> 1) + (col >> 1)] = pk2(v2, v3);
            } else {
                int bb = r0 >> 10;
                int sr = r0 & 1023;
                int h  = (col >> 6) & 7;
                size_t bh = (size_t)(bb * 8 + h);
                if (col < 512) {
                    v0 *= 0.125f; v1 *= 0.125f; v2 *= 0.125f; v3 *= 0.125f;
                    size_t base = (bh * 1024 + sr) * 32 + ((col & 63) >> 1);
                    Qpk[base]            = pk2(v0, v1);
                    Qpk[base + 8 * 32]   = pk2(v2, v3);
                } else if (col < 1024) {
                    size_t base = (bh * 1024 + sr) * 32 + ((col & 63) >> 1);
                    Kpk[base]            = pk2(v0, v1);
                    Kpk[base + 8 * 32]   = pk2(v2, v3);
                } else {
                    size_t base = (bh * 1024 + sr) * 64 + (col & 63);
                    *(float2*)(Vtmp + base)            = make_float2(v0, v1);
                    *(float2*)(Vtmp + base + 8 * 64)   = make_float2(v2, v3);
                }
            }
        }
    }
}

// ============================ V repack (key-pair packing) ===================
__global__ __launch_bounds__(256)
void repack_v_kernel(const float* __restrict__ Vtmp, uint32_t* __restrict__ Vpk) {
    int bh  = blockIdx.x >> 3;
    int kp0 = (blockIdx.x & 7) * 64;
    const float* src = Vtmp + (size_t)bh * 1024 * 64;
    uint32_t* dst = Vpk + ((size_t)bh * 512 + kp0) * 64;
    for (int i = threadIdx.x; i < 64 * 64; i += 256) {
        int kpl = i >> 6;
        int d   = i & 63;
        int key0 = 2 * (kp0 + kpl);
        dst[(size_t)kpl * 64 + d] = pk2(src[(size_t)key0 * 64 + d],
                                        src[(size_t)(key0 + 1) * 64 + d]);
    }
}

// ============================ flash attention (bf16 mma) ====================
// Q/K: [bh][row][32] bf16x2 (d-pairs); V: [bh][keypair][64] bf16x2.
// Block 256 thr (8 warps), 128 q-rows; K/V double-buffered cp.async.
#define QP  36
#define KPT 36
#define VPT 72
#define KTILE (64 * KPT)
#define VTILE (32 * VPT)
#define FSTG (KTILE + VTILE)
#define QTILE (128 * QP)
#define FLASH_SMEM ((2 * FSTG + QTILE) * 4)

__global__ __launch_bounds__(256)
void flash_bf16_kernel(const uint32_t* __restrict__ Qpk,
                       const uint32_t* __restrict__ Kpk,
                       const uint32_t* __restrict__ Vpk,
                       uint32_t* __restrict__ ctxpk,
                       const int* __restrict__ dlen) {
    extern __shared__ uint32_t smu[];

    const int qt = blockIdx.x;
    const int bh = blockIdx.y;
    const int b  = bh >> 3;
    const int len = dlen[b];
    const int nk = (len + 63) >> 6;

    const int tid = threadIdx.x;
    const int warp = tid >> 5;
    const int lane = tid & 31;
    const int qid = lane >> 2;
    const int tq  = lane & 3;
    const int m0  = warp * 16;

    const uint32_t* Qg = Qpk + ((size_t)bh * 1024 + qt * 128) * 32;
    const uint32_t* Kg = Kpk + (size_t)bh * 1024 * 32;
    const uint32_t* Vg = Vpk + (size_t)bh * 512 * 64;

    uint32_t* Qs = smu + 2 * FSTG;
    uint32_t smbase = (uint32_t)__cvta_generic_to_shared(smu);
    uint32_t qbase  = smbase + 2 * FSTG * 4;

    // group 1: Q tile
#pragma unroll
    for (int u = 0; u < 4; u++) {
        int f = tid + u * 256;
        int r = f >> 3, c4 = (f & 7) << 2;
        cpa16(qbase + (r * QP + c4) * 4, Qg + (size_t)r * 32 + c4);
    }
    CP_COMMIT();
    // group 2: K/V tile 0
    {
        uint32_t kd = smbase, vd = smbase + KTILE * 4;
#pragma unroll
        for (int u = 0; u < 2; u++) {
            int f = tid + u * 256;
            int rk = f >> 3, ck = (f & 7) << 2;
            cpa16(kd + (rk * KPT + ck) * 4, Kg + (size_t)rk * 32 + ck);
            int rv = f >> 4, cv = (f & 15) << 2;
            cpa16(vd + (rv * VPT + cv) * 4, Vg + (size_t)rv * 64 + cv);
        }
        CP_COMMIT();
    }
    CP_WAIT(1);
    __syncthreads();

    // Q fragments: 4 d-chunks of k16
    unsigned aq[4][4];
#pragma unroll
    for (int s = 0; s < 4; s++) {
        aq[s][0] = Qs[(m0 + qid) * QP + s * 8 + tq];
        aq[s][1] = Qs[(m0 + qid + 8) * QP + s * 8 + tq];
        aq[s][2] = Qs[(m0 + qid) * QP + s * 8 + tq + 4];
        aq[s][3] = Qs[(m0 + qid + 8) * QP + s * 8 + tq + 4];
    }
    uint32_t* Pw = Qs + m0 * QP;     // per-warp P tile [16][QP]

    float mr0 = -1e30f, mr1 = -1e30f, lr0 = 0.f, lr1 = 0.f;
    float O[8][4];
#pragma unroll
    for (int n = 0; n < 8; n++)
#pragma unroll
        for (int c = 0; c < 4; c++) O[n][c] = 0.f;

    for (int kt = 0; kt < nk; kt++) {
        __syncthreads();
        if (kt + 1 < nk) {
            uint32_t sb = smbase + ((kt + 1) & 1) * FSTG * 4;
            uint32_t kd = sb, vd = sb + KTILE * 4;
            const uint32_t* kg = Kg + (size_t)(kt + 1) * 64 * 32;
            const uint32_t* vg = Vg + (size_t)(kt + 1) * 32 * 64;
#pragma unroll
            for (int u = 0; u < 2; u++) {
                int f = tid + u * 256;
                int rk = f >> 3, ck = (f & 7) << 2;
                cpa16(kd + (rk * KPT + ck) * 4, kg + (size_t)rk * 32 + ck);
                int rv = f >> 4, cv = (f & 15) << 2;
                cpa16(vd + (rv * VPT + cv) * 4, vg + (size_t)rv * 64 + cv);
            }
            CP_COMMIT();
            CP_WAIT(1);
        } else {
            CP_WAIT(0);
        }
        __syncthreads();

        const uint32_t* Ks = smu + (kt & 1) * FSTG;
        const uint32_t* Vs = Ks + KTILE;

        // ---- S = Q @ K^T (Q pre-scaled) ----
        float c[8][4];
#pragma unroll
        for (int n = 0; n < 8; n++)
#pragma unroll
            for (int j = 0; j < 4; j++) c[n][j] = 0.f;

#pragma unroll
        for (int s = 0; s < 4; s++) {
#pragma unroll
            for (int n = 0; n < 8; n++) {
                unsigned b0 = Ks[(n * 8 + qid) * KPT + s * 8 + tq];
                unsigned b1 = Ks[(n * 8 + qid) * KPT + s * 8 + tq + 4];
                MMA_BF16(c[n][0], c[n][1], c[n][2], c[n][3],
                         aq[s][0], aq[s][1], aq[s][2], aq[s][3], b0, b1);
            }
        }

        // ---- mask + online softmax ----
        const int cb = kt * 64 + 2 * tq;
        float mx0 = -1e30f, mx1 = -1e30f;
#pragma unroll
        for (int n = 0; n < 8; n++) {
            int c0 = cb + n * 8, c1 = c0 + 1;
            if (c0 >= len) { c[n][0] = -1e30f; c[n][2] = -1e30f; }
            if (c1 >= len) { c[n][1] = -1e30f; c[n][3] = -1e30f; }
            mx0 = fmaxf(mx0, fmaxf(c[n][0], c[n][1]));
            mx1 = fmaxf(mx1, fmaxf(c[n][2], c[n][3]));
        }
        mx0 = fmaxf(mx0, __shfl_xor_sync(0xffffffffu, mx0, 1));
        mx0 = fmaxf(mx0, __shfl_xor_sync(0xffffffffu, mx0, 2));
        mx1 = fmaxf(mx1, __shfl_xor_sync(0xffffffffu, mx1, 1));
        mx1 = fmaxf(mx1, __shfl_xor_sync(0xffffffffu, mx1, 2));

        float mn0 = fmaxf(mr0, mx0), mn1 = fmaxf(mr1, mx1);
        float al0 = __expf(mr0 - mn0), al1 = __expf(mr1 - mn1);
        float rs0 = 0.f, rs1 = 0.f;
#pragma unroll
        for (int n = 0; n < 8; n++) {
            c[n][0] = __expf(c[n][0] - mn0);
            c[n][1] = __expf(c[n][1] - mn0);
            c[n][2] = __expf(c[n][2] - mn1);
            c[n][3] = __expf(c[n][3] - mn1);
            rs0 += c[n][0] + c[n][1];
            rs1 += c[n][2] + c[n][3];
        }
        rs0 += __shfl_xor_sync(0xffffffffu, rs0, 1);
        rs0 += __shfl_xor_sync(0xffffffffu, rs0, 2);
        rs1 += __shfl_xor_sync(0xffffffffu, rs1, 1);
        rs1 += __shfl_xor_sync(0xffffffffu, rs1, 2);
        lr0 = lr0 * al0 + rs0;
        lr1 = lr1 * al1 + rs1;
        mr0 = mn0; mr1 = mn1;
#pragma unroll
        for (int n = 0; n < 8; n++) {
            O[n][0] *= al0; O[n][1] *= al0;
            O[n][2] *= al1; O[n][3] *= al1;
        }

        // ---- write P packed (per-warp region) ----
#pragma unroll
        for (int n = 0; n < 8; n++) {
            Pw[qid * QP + 4 * n + tq]       = pk2(c[n][0], c[n][1]);
            Pw[(qid + 8) * QP + 4 * n + tq] = pk2(c[n][2], c[n][3]);
        }
        __syncwarp();

        // ---- O += P @ V ----
#pragma unroll
        for (int s = 0; s < 4; s++) {
            unsigned ap0 = Pw[qid * QP + s * 8 + tq];
            unsigned ap1 = Pw[(qid + 8) * QP + s * 8 + tq];
            unsigned ap2 = Pw[qid * QP + s * 8 + tq + 4];
            unsigned ap3 = Pw[(qid + 8) * QP + s * 8 + tq + 4];
#pragma unroll
            for (int n = 0; n < 8; n++) {
                unsigned b0 = Vs[(s * 8 + tq) * VPT + n * 8 + qid];
                unsigned b1 = Vs[(s * 8 + tq + 4) * VPT + n * 8 + qid];
                MMA_BF16(O[n][0], O[n][1], O[n][2], O[n][3],
                         ap0, ap1, ap2, ap3, b0, b1);
            }
        }
        __syncwarp();
    }

    // ---- epilogue: packed ctx ----
    float inv0 = 1.f / lr0, inv1 = 1.f / lr1;
    int h = bh & 7;
    size_t row0 = (size_t)(b * Sn + qt * 128 + m0 + qid);
#pragma unroll
    for (int n = 0; n < 8; n++) {
        int dp = h * 32 + 4 * n + tq;
        ctxpk[row0 * 256 + dp]       = pk2(O[n][0] * inv0, O[n][1] * inv0);
        ctxpk[(row0 + 8) * 256 + dp] = pk2(O[n][2] * inv1, O[n][3] * inv1);
    }
}

// ============================ add + layernorm ===============================
__device__ __forceinline__ float blk_sum_128(float v, float* red) {
#pragma unroll
    for (int o = 16; o; o >>= 1) v += __shfl_xor_sync(0xffffffffu, v, o);
    __syncthreads();
    if ((threadIdx.x & 31) == 0) red[threadIdx.x >> 5] = v;
    __syncthreads();
    return red[0] + red[1] + red[2] + red[3];
}

__global__ __launch_bounds__(128)
void add_ln_kernel(float* __restrict__ x, uint32_t* __restrict__ xpk,
                   const float* __restrict__ hh,
                   const float* __restrict__ g, const float* __restrict__ be) {
    __shared__ float red[4];
    int row = blockIdx.x;
    int t = threadIdx.x;
    size_t off = (size_t)row * 512 + t * 4;
    float4 xv = *(float4*)(x + off);
    float4 hv = *(const float4*)(hh + off);
    float v0 = xv.x + hv.x, v1 = xv.y + hv.y, v2 = xv.z + hv.z, v3 = xv.w + hv.w;
    float mean = blk_sum_128(v0 + v1 + v2 + v3, red) * (1.f / 512.f);
    float d0 = v0 - mean, d1 = v1 - mean, d2 = v2 - mean, d3 = v3 - mean;
    float var = blk_sum_128(d0 * d0 + d1 * d1 + d2 * d2 + d3 * d3, red) * (1.f / 512.f);
    float rstd = rsqrtf(var + 1e-5f);
    float4 gv = *(const float4*)(g + t * 4);
    float4 bv = *(const float4*)(be + t * 4);
    float4 o;
    o.x = d0 * rstd * gv.x + bv.x;
    o.y = d1 * rstd * gv.y + bv.y;
    o.z = d2 * rstd * gv.z + bv.z;
    o.w = d3 * rstd * gv.w + bv.w;
    *(float4*)(x + off) = o;
    uint2 p;
    p.x = pk2(o.x, o.y);
    p.y = pk2(o.z, o.w);
    *(uint2*)(xpk + (size_t)row * 256 + t * 2) = p;
}

// ============================ final head ====================================
#define HEAD_SMEM (512 * 32 * 4)

__global__ __launch_bounds__(256)
void final_logits_kernel(const float* __restrict__ x, const float* __restrict__ addr,
                         const float* __restrict__ poi, const int* __restrict__ atype,
                         const float* __restrict__ Wa, const float* __restrict__ ba,
                         const float* __restrict__ Wout, const float* __restrict__ Wcomb,
                         const int* __restrict__ dlen, float* __restrict__ logits) {
    extern __shared__ float ws[];
    for (int i = threadIdx.x; i < 512 * 32; i += 256) ws[i] = Wout[i];
    __syncthreads();

    const int warp = threadIdx.x >> 5;
    const int lane = threadIdx.x & 31;
    const float wc = Wcomb[lane];

    for (int tok = blockIdx.x * 8 + warp; tok < BSn; tok += gridDim.x * 8) {
        int b = tok >> 10;
        int s = tok & 1023;
        int t = atype[b];
        float aj = ba[lane]
                 + addr[b]        * Wa[lane]
                 + poi[t * 3 + 0] * Wa[32 + lane]
                 + poi[t * 3 + 1] * Wa[64 + lane]
                 + poi[t * 3 + 2] * Wa[96 + lane];
        const float* xr = x + (size_t)tok * 512;
        float acc = 0.f;
        for (int d0 = 0; d0 < 512; d0 += 32) {
            float xv = xr[d0 + lane];
#pragma unroll
            for (int j = 0; j < 32; j++)
                acc += __shfl_sync(0xffffffffu, xv, j) * ws[(d0 + j) * 32 + lane];
        }
        float tv = tanhf(acc + aj) * wc;
#pragma unroll
        for (int o = 16; o; o >>= 1) tv += __shfl_xor_sync(0xffffffffu, tv, o);
        if (lane == 0) logits[tok] = (s < dlen[b]) ? tv : -1e9f;
    }
}

__global__ __launch_bounds__(256)
void logsoftmax_kernel(const float* __restrict__ logits, const int* __restrict__ dlen,
                       float* __restrict__ out) {
    __shared__ float red[8];
    int b = blockIdx.x;
    int len = dlen[b];
    const float* lg = logits + (size_t)b * Sn;
    float mx = -1e30f;
    for (int s = threadIdx.x; s < len; s += 256) mx = fmaxf(mx, lg[s]);
#pragma unroll
    for (int o = 16; o; o >>= 1) mx = fmaxf(mx, __shfl_xor_sync(0xffffffffu, mx, o));
    if ((threadIdx.x & 31) == 0) red[threadIdx.x >> 5] = mx;
    __syncthreads();
    mx = red[0];
#pragma unroll
    for (int w = 1; w < 8; w++) mx = fmaxf(mx, red[w]);
    __syncthreads();
    float sum = 0.f;
    for (int s = threadIdx.x; s < len; s += 256) sum += expf(lg[s] - mx);
#pragma unroll
    for (int o = 16; o; o >>= 1) sum += __shfl_xor_sync(0xffffffffu, sum, o);
    if ((threadIdx.x & 31) == 0) red[threadIdx.x >> 5] = sum;
    __syncthreads();
    sum = red[0] + red[1] + red[2] + red[3] + red[4] + red[5] + red[6] + red[7];
    float lse = logf(sum) + mx;
    for (int s = threadIdx.x; s < Sn; s += 256)
        out[(size_t)b * Sn + s] = (s < len) ? (lg[s] - lse) : 0.f;
}

// ============================ launch ========================================
extern "C" void kernel_launch(void* const* d_in, const int* in_sizes, int n_in,
                              void* d_out, int out_size) {
    const float* addr  = (const float*)d_in[0];
    const float* loc   = (const float*)d_in[1];
    const float* tdist = (const float*)d_in[2];
    const float* Wtd   = (const float*)d_in[3];
    const float* btd   = (const float*)d_in[4];
    const float* Wemb  = (const float*)d_in[5];
    const float* bemb  = (const float*)d_in[6];
    const float* Wqkv  = (const float*)d_in[7];
    const float* bqkv  = (const float*)d_in[8];
    const float* Wo    = (const float*)d_in[9];
    const float* bo    = (const float*)d_in[10];
    const float* ln1g  = (const float*)d_in[11];
    const float* ln1b  = (const float*)d_in[12];
    const float* W1    = (const float*)d_in[13];
    const float* b1    = (const float*)d_in[14];
    const float* W2    = (const float*)d_in[15];
    const float* b2    = (const float*)d_in[16];
    const float* ln2g  = (const float*)d_in[17];
    const float* ln2b  = (const float*)d_in[18];
    const float* poi   = (const float*)d_in[19];
    const float* Wa    = (const float*)d_in[20];
    const float* ba    = (const float*)d_in[21];
    const float* Wout  = (const float*)d_in[22];
    const float* Wcomb = (const float*)d_in[23];
    const int*   atype = (const int*)d_in[24];
    const int*   dlen  = (const int*)d_in[25];
    float* out = (float*)d_out;

    float *x, *t1, *vtmp, *lg;
    uint32_t *xpk, *qpk, *kpk, *vpk, *ctxpk, *t2pk, *wqkv, *wo, *w1, *w2;
    cudaGetSymbolAddress((void**)&x,     g_x);
    cudaGetSymbolAddress((void**)&xpk,   g_xpk);
    cudaGetSymbolAddress((void**)&qpk,   g_qpk);
    cudaGetSymbolAddress((void**)&kpk,   g_kpk);
    cudaGetSymbolAddress((void**)&vtmp,  g_vtmp);
    cudaGetSymbolAddress((void**)&vpk,   g_vpk);
    cudaGetSymbolAddress((void**)&ctxpk, g_ctxpk);
    cudaGetSymbolAddress((void**)&t1,    g_t1);
    cudaGetSymbolAddress((void**)&t2pk,  g_t2pk);
    cudaGetSymbolAddress((void**)&wqkv,  g_wqkv);
    cudaGetSymbolAddress((void**)&wo,    g_wo);
    cudaGetSymbolAddress((void**)&w1,    g_w1);
    cudaGetSymbolAddress((void**)&w2,    g_w2);
    cudaGetSymbolAddress((void**)&lg,    g_logits);

    cudaFuncSetAttribute(flash_bf16_kernel,
                         cudaFuncAttributeMaxDynamicSharedMemorySize, FLASH_SMEM);
    cudaFuncSetAttribute(final_logits_kernel,
                         cudaFuncAttributeMaxDynamicSharedMemorySize, HEAD_SMEM);

    // pack all weights (bf16x2 along K)
    pack_w_kernel<<<(Ln * 256 * 1536 + 255) / 256, 256>>>(Wqkv, wqkv, Ln * 256, 1536);
    pack_w_kernel<<<(Ln * 256 * 512 + 255) / 256, 256>>>(Wo, wo, Ln * 256, 512);
    pack_w_kernel<<<(Ln * 256 * 512 + 255) / 256, 256>>>(W1, w1, Ln * 256, 512);
    pack_w_kernel<<<(Ln * 256 * 512 + 255) / 256, 256>>>(W2, w2, Ln * 256, 512);

    embed_kernel<<<BSn, 128>>>(loc, tdist, Wtd, btd, Wemb, bemb, x, xpk);

    for (int l = 0; l < Ln; l++) {
        bf16_gemm<2><<<dim3(12, 256), 256>>>(
            xpk, wqkv + (size_t)l * 256 * 1536, bqkv + l * 1536,
            nullptr, nullptr, qpk, kpk, vtmp, BSn, 1536, 256);
        repack_v_kernel<<<256 * 8, 256>>>(vtmp, vpk);
        flash_bf16_kernel<<<dim3(8, Bn * Hn), 256, FLASH_SMEM>>>(qpk, kpk, vpk,
                                                                 ctxpk, dlen);
        bf16_gemm<0><<<dim3(4, 256), 256>>>(
            ctxpk, wo + (size_t)l * 256 * 512, bo + l * 512,
            t1, nullptr, nullptr, nullptr, nullptr, BSn, 512, 256);
        add_ln_kernel<<<BSn, 128>>>(x, xpk, t1, ln1g + l * 512, ln1b + l * 512);
        bf16_gemm<1><<<dim3(4, 256), 256>>>(
            xpk, w1 + (size_t)l * 256 * 512, b1 + l * 512,
            nullptr, t2pk, nullptr, nullptr, nullptr, BSn, 512, 256);
        bf16_gemm<0><<<dim3(4, 256), 256>>>(
            t2pk, w2 + (size_t)l * 256 * 512, b2 + l * 512,
            t1, nullptr, nullptr, nullptr, nullptr, BSn, 512, 256);
        add_ln_kernel<<<BSn, 128>>>(x, xpk, t1, ln2g + l * 512, ln2b + l * 512);
    }

    final_logits_kernel<<<512, 256, HEAD_SMEM>>>(x, addr, poi, atype, Wa, ba,
                                                 Wout, Wcomb, dlen, lg);
    logsoftmax_kernel<<<Bn, 256>>>(lg, dlen, out);
}